// round 8
// baseline (speedup 1.0000x reference)
#include <cuda_runtime.h>
#include <cuda_bf16.h>
#include <math.h>
#include <stdint.h>

#define NN 8
#define CI 128
#define CO 128
#define HH 128
#define WW 128
#define HWSZ (HH*WW)
#define EPS 1e-5f

#define KC 64                  // ci per chunk
#define NCHUNK 2
#define NTAP 9
#define NSTAGE (NCHUNK*NTAP)   // 18
#define ROWS_PER_CTA 2
#define BROWS 4                // input rows (2 output rows + halo)
#define BCOLS 130              // 128 + 2 halo
#define BPIX (BROWS*BCOLS)     // 520

#define CONV_THREADS 512       // 16 warps

// smem layout (bytes): A double buffer (hi 8K + lo 8K each), then B hi/lo
#define SMEM_ABUF   16384
#define SMEM_B_HI   32768
#define SMEM_B_SZ   (BPIX*128)            // 66560
#define SMEM_B_LO   (SMEM_B_HI + SMEM_B_SZ)
#define SMEM_TOTAL  (SMEM_B_LO + SMEM_B_SZ)   // 165888

// scratch
__device__ float g_y[(size_t)NN*CO*HH*WW];
__device__ float g_sum[NN*CO];
__device__ float g_sq[NN*CO];
__device__ unsigned char g_wpack[NSTAGE*32768];  // [chunk*9+tap]: hi 16KB + lo 16KB, swizzled [co][ci]

// ---------------- helpers ----------------
__device__ __forceinline__ uint32_t smem_u32(const void* p) {
    uint32_t a;
    asm("{ .reg .u64 t; cvta.to.shared.u64 t, %1; cvt.u32.u64 %0, t; }" : "=r"(a) : "l"(p));
    return a;
}
__host__ __device__ __forceinline__ uint32_t swz128(uint32_t off) { return off ^ ((off >> 3) & 0x70); }

__device__ __forceinline__ void ldsm4(uint32_t* r, uint32_t addr) {
    asm volatile("ldmatrix.sync.aligned.m8n8.x4.shared.b16 {%0,%1,%2,%3}, [%4];"
                 : "=r"(r[0]), "=r"(r[1]), "=r"(r[2]), "=r"(r[3]) : "r"(addr));
}
__device__ __forceinline__ void mma16816(float* d, const uint32_t* a, uint32_t b0, uint32_t b1) {
    asm volatile("mma.sync.aligned.m16n8k16.row.col.f32.bf16.bf16.f32 "
                 "{%0,%1,%2,%3}, {%4,%5,%6,%7}, {%8,%9}, {%0,%1,%2,%3};"
                 : "+f"(d[0]), "+f"(d[1]), "+f"(d[2]), "+f"(d[3])
                 : "r"(a[0]), "r"(a[1]), "r"(a[2]), "r"(a[3]), "r"(b0), "r"(b1));
}
__device__ __forceinline__ void cp_async16(uint32_t dst, const void* src) {
    asm volatile("cp.async.cg.shared.global [%0], [%1], 16;" :: "r"(dst), "l"(src));
}
__device__ __forceinline__ void cp_commit()  { asm volatile("cp.async.commit_group;"); }
__device__ __forceinline__ void cp_waitall() { asm volatile("cp.async.wait_group 0;" ::: "memory"); }
__device__ __forceinline__ void sts16(uint32_t addr, unsigned short v) {
    asm volatile("st.shared.u16 [%0], %1;" :: "r"(addr), "h"(v));
}

// ---------------- weight prepack (+ zero sums folded in) ----------------
__global__ void prepack_kernel(const float* __restrict__ w) {
    int idx = blockIdx.x * blockDim.x + threadIdx.x;   // (co*CI + ci)*9 + t
    if (idx < NN*CO) { g_sum[idx] = 0.0f; g_sq[idx] = 0.0f; }
    if (idx >= CO*CI*NTAP) return;
    int t  = idx % 9;
    int ci = (idx / 9) % CI;
    int co = idx / (9*CI);
    float v = w[idx];
    __nv_bfloat16 hi = __float2bfloat16(v);
    __nv_bfloat16 lo = __float2bfloat16(v - __bfloat162float(hi));
    int chunk = ci >> 6, cil = ci & 63;
    int img = chunk*NTAP + t;
    uint32_t off = swz128((uint32_t)co*128 + (uint32_t)cil*2);
    *(__nv_bfloat16*)(g_wpack + (size_t)img*32768 + off)         = hi;
    *(__nv_bfloat16*)(g_wpack + (size_t)img*32768 + 16384 + off) = lo;
}

// ---------------- conv: implicit GEMM via mma.sync bf16 (3-pass hi/lo) ----------------
// 512 threads = 16 warps. CTA: 64 co x 256 pixels (2 output rows).
// Warp tile: 32 co x 32 pixels (2 x 4 mma tiles) -> 32 acc regs/thread.
__global__ __launch_bounds__(CONV_THREADS, 1)
void conv_mma_kernel(const float* __restrict__ x, const float* __restrict__ bias)
{
    extern __shared__ __align__(1024) unsigned char smem[];
    const uint32_t sbase = smem_u32(smem);
    const int tid    = threadIdx.x;
    const int lane   = tid & 31;
    const int w      = tid >> 5;       // 0..15
    const int warp_m = w >> 3;         // 0..1 : 32 co each
    const int warp_n = w & 7;          // 0..7 : 32 pixels each
    const int hrow   = warp_n >> 2;    // output row within CTA (0/1)
    const int colb   = (warp_n & 3) * 32;

    const int cog = blockIdx.x & 1;             // co half (0/1)
    const int r0  = ((blockIdx.x >> 1) & 63) * ROWS_PER_CTA;
    const int n   = blockIdx.x >> 7;            // image

    const int mtx   = lane >> 3;       // ldmatrix matrix id this lane addresses
    const int rowin = lane & 7;

    // A ldmatrix per-thread constants (row = co_local, k-contiguous 128B rows, SW128)
    const uint32_t kca = (uint32_t)((mtx >> 1) * 16);
    uint32_t aoff[2], axr[2];
    #pragma unroll
    for (int mt = 0; mt < 2; mt++) {
        int col = warp_m*32 + mt*16 + (mtx & 1)*8 + rowin;   // co within the 64-slice
        aoff[mt] = (uint32_t)col * 128;
        axr[mt]  = (uint32_t)(col & 7) << 4;
    }
    const uint32_t kcb = (uint32_t)((mtx & 1) * 16);

    float acc[2][4][4];
    #pragma unroll
    for (int mt = 0; mt < 2; mt++)
        #pragma unroll
        for (int nt = 0; nt < 4; nt++)
            #pragma unroll
            for (int i = 0; i < 4; i++)
                acc[mt][nt][i] = 0.0f;

    // prologue: async-load A stage 0 slice (hi 8KB + lo 8KB)
    {
        const uint4* sh = (const uint4*)(g_wpack + (size_t)cog*8192);
        const uint4* sl = (const uint4*)(g_wpack + 16384 + (size_t)cog*8192);
        cp_async16(sbase + (uint32_t)tid*16,        sh + tid);
        cp_async16(sbase + 8192 + (uint32_t)tid*16, sl + tid);
        cp_commit();
    }

    for (int s = 0; s < NSTAGE; s++) {
        const int chunk = s / NTAP;
        const int tap   = s - chunk*NTAP;

        if (tap == 0) {
            __syncthreads();   // all warps done reading previous chunk's B
            const int cb = chunk * KC;
            for (int u = w; u < BROWS*KC; u += 16) {
                const int rho = u >> 6;          // 0..3
                const int cil = u & 63;
                const int gr  = r0 - 1 + rho;
                const float* xp = x + (((size_t)n*CI + (cb + cil)) * HH + gr) * WW;
                const bool rok = (gr >= 0) & (gr < HH);
                #pragma unroll
                for (int c0 = 0; c0 < 160; c0 += 32) {
                    const int cc = c0 + lane;
                    if (cc < BCOLS) {
                        const int gc = cc - 1;
                        float v = (rok && gc >= 0 && gc < WW) ? __ldg(xp + gc) : 0.0f;
                        __nv_bfloat16 hi = __float2bfloat16(v);
                        __nv_bfloat16 lo = __float2bfloat16(v - __bfloat162float(hi));
                        const uint32_t off = swz128((uint32_t)(rho*BCOLS + cc)*128 + (uint32_t)cil*2);
                        sts16(sbase + SMEM_B_HI + off, *(unsigned short*)&hi);
                        sts16(sbase + SMEM_B_LO + off, *(unsigned short*)&lo);
                    }
                }
            }
        }

        cp_waitall();          // A[s] landed
        __syncthreads();       // A[s] + B visible; prior compute finished

        if (s + 1 < NSTAGE) {  // prefetch A[s+1] slice into the other buffer
            const uint4* sh = (const uint4*)(g_wpack + (size_t)(s+1)*32768 + (size_t)cog*8192);
            const uint4* sl = (const uint4*)(g_wpack + (size_t)(s+1)*32768 + 16384 + (size_t)cog*8192);
            const uint32_t dst = sbase + (uint32_t)((s+1) & 1) * SMEM_ABUF;
            cp_async16(dst + (uint32_t)tid*16,        sh + tid);
            cp_async16(dst + 8192 + (uint32_t)tid*16, sl + tid);
            cp_commit();
        }

        // ---- compute stage s ----
        const uint32_t a_hi = sbase + (uint32_t)(s & 1) * SMEM_ABUF;
        const int kh = tap / 3, kw = tap - kh*3;
        uint32_t boff[2], bxr[2];
        #pragma unroll
        for (int p = 0; p < 2; p++) {
            int pix = (hrow + kh)*BCOLS + colb + p*16 + (mtx >> 1)*8 + rowin + kw;
            boff[p] = (uint32_t)pix * 128;
            bxr[p]  = (uint32_t)(pix & 7) << 4;
        }

        #pragma unroll
        for (int ks = 0; ks < 4; ks++) {
            uint32_t ah[2][4], al[2][4];
            #pragma unroll
            for (int mt = 0; mt < 2; mt++) {
                const uint32_t ka = (uint32_t)ks*32 + kca;
                const uint32_t ad = a_hi + aoff[mt] + (ka ^ axr[mt]);
                ldsm4(ah[mt], ad);
                ldsm4(al[mt], ad + 8192);
            }
            #pragma unroll
            for (int p = 0; p < 2; p++) {
                uint32_t bh[4], bl[4];
                const uint32_t kb = (uint32_t)ks*32 + kcb;
                const uint32_t bd = sbase + SMEM_B_HI + boff[p] + (kb ^ bxr[p]);
                ldsm4(bh, bd);
                ldsm4(bl, bd + SMEM_B_SZ);
                #pragma unroll
                for (int mt = 0; mt < 2; mt++)
                    #pragma unroll
                    for (int q = 0; q < 2; q++) {
                        float* a4 = acc[mt][p*2 + q];
                        mma16816(a4, ah[mt], bh[q*2], bh[q*2+1]);  // hi*hi
                        mma16816(a4, al[mt], bh[q*2], bh[q*2+1]);  // lo(W)*hi(X)
                        mma16816(a4, ah[mt], bl[q*2], bl[q*2+1]);  // hi(W)*lo(X)
                    }
            }
        }
    }

    // ---- epilogue: bias + store + instance sums ----
    const int g  = lane >> 2;
    const int tg = lane & 3;
    const int row = r0 + hrow;
    #pragma unroll
    for (int mt = 0; mt < 2; mt++) {
        const int co0 = cog*64 + warp_m*32 + mt*16 + g;
        const int co1 = co0 + 8;
        const float b0 = __ldg(bias + co0);
        const float b1 = __ldg(bias + co1);
        float* yp0 = g_y + ((size_t)(n*CO + co0) * HH + row) * WW;
        float* yp1 = g_y + ((size_t)(n*CO + co1) * HH + row) * WW;
        float s0 = 0.f, q0 = 0.f, s1 = 0.f, q1 = 0.f;
        #pragma unroll
        for (int nt = 0; nt < 4; nt++) {
            const int pix = colb + nt*8 + 2*tg;
            float v0 = acc[mt][nt][0] + b0;
            float v1 = acc[mt][nt][1] + b0;
            float v2 = acc[mt][nt][2] + b1;
            float v3 = acc[mt][nt][3] + b1;
            float2 o0 = {v0, v1}, o1 = {v2, v3};
            *(float2*)(yp0 + pix) = o0;
            *(float2*)(yp1 + pix) = o1;
            s0 += v0 + v1;  q0 += v0*v0 + v1*v1;
            s1 += v2 + v3;  q1 += v2*v2 + v3*v3;
        }
        #pragma unroll
        for (int o = 1; o <= 2; o <<= 1) {
            s0 += __shfl_xor_sync(0xffffffffu, s0, o);
            q0 += __shfl_xor_sync(0xffffffffu, q0, o);
            s1 += __shfl_xor_sync(0xffffffffu, s1, o);
            q1 += __shfl_xor_sync(0xffffffffu, q1, o);
        }
        if (tg == 0) {
            atomicAdd(&g_sum[n*CO + co0], s0);
            atomicAdd(&g_sq [n*CO + co0], q0);
            atomicAdd(&g_sum[n*CO + co1], s1);
            atomicAdd(&g_sq [n*CO + co1], q1);
        }
    }
}

// ---------------- normalize + affine + ReLU ----------------
__global__ __launch_bounds__(256)
void norm_kernel(const float* __restrict__ gamma, const float* __restrict__ beta,
                 float* __restrict__ out)
{
    const int inst = blockIdx.x;
    const int c = inst & (CO - 1);
    const float mean = g_sum[inst] * (1.0f / HWSZ);
    const float var  = g_sq[inst] * (1.0f / HWSZ) - mean * mean;
    const float rstd = rsqrtf(var + EPS);
    const float sc = rstd * gamma[c];
    const float sh = beta[c] - mean * sc;

    const float4* yp = (const float4*)(g_y + (size_t)inst * HWSZ);
    float4* op = (float4*)(out + (size_t)inst * HWSZ);
    for (int i = threadIdx.x; i < HWSZ/4; i += 256) {
        float4 v = yp[i];
        float4 o;
        o.x = fmaxf(fmaf(v.x, sc, sh), 0.0f);
        o.y = fmaxf(fmaf(v.y, sc, sh), 0.0f);
        o.z = fmaxf(fmaf(v.z, sc, sh), 0.0f);
        o.w = fmaxf(fmaf(v.w, sc, sh), 0.0f);
        op[i] = o;
    }
}

extern "C" void kernel_launch(void* const* d_in, const int* in_sizes, int n_in,
                              void* d_out, int out_size)
{
    const float* x      = (const float*)d_in[0];
    const float* weight = (const float*)d_in[1];
    const float* bias   = (const float*)d_in[2];
    const float* gamma  = (const float*)d_in[3];
    const float* beta   = (const float*)d_in[4];
    float* out = (float*)d_out;

    cudaFuncSetAttribute(conv_mma_kernel, cudaFuncAttributeMaxDynamicSharedMemorySize, SMEM_TOTAL);

    prepack_kernel<<<(CO*CI*NTAP + 255)/256, 256>>>(weight);
    conv_mma_kernel<<<NN*(HH/ROWS_PER_CTA)*2, CONV_THREADS, SMEM_TOTAL>>>(x, bias);
    norm_kernel<<<NN*CO, 256>>>(gamma, beta, out);
}

// round 9
// speedup vs baseline: 1.4261x; 1.4261x over previous
#include <cuda_runtime.h>
#include <cuda_fp16.h>
#include <math.h>
#include <stdint.h>

#define NN 8
#define CI 128
#define CO 128
#define HH 128
#define WW 128
#define HWSZ (HH*WW)
#define EPS 1e-5f

#define KC 64                  // ci per chunk
#define NCHUNK 2
#define NTAP 9
#define NSTAGE (NCHUNK*NTAP)   // 18
#define ROWS_PER_CTA 2
#define BROWS 4                // input rows (2 output rows + halo)
#define BCOLS 130              // 128 + 2 halo
#define BPIX (BROWS*BCOLS)     // 520

#define CONV_THREADS 512       // 16 warps

// smem layout (bytes): A double buffer (hi 16K + lo 16K each), then B (fp16, single)
#define SMEM_ABUF   32768
#define SMEM_B      65536
#define SMEM_B_SZ   (BPIX*128)            // 66560
#define SMEM_TOTAL  (SMEM_B + SMEM_B_SZ)  // 132096

// scratch
__device__ float g_y[(size_t)NN*CO*HH*WW];
__device__ float g_sum[NN*CO];
__device__ float g_sq[NN*CO];
__device__ unsigned char g_wpack[NSTAGE*32768];  // [chunk*9+tap]: hi 16KB + lo 16KB, swizzled [co][ci] fp16

// ---------------- helpers ----------------
__device__ __forceinline__ uint32_t smem_u32(const void* p) {
    uint32_t a;
    asm("{ .reg .u64 t; cvta.to.shared.u64 t, %1; cvt.u32.u64 %0, t; }" : "=r"(a) : "l"(p));
    return a;
}
__host__ __device__ __forceinline__ uint32_t swz128(uint32_t off) { return off ^ ((off >> 3) & 0x70); }

__device__ __forceinline__ void ldsm4(uint32_t* r, uint32_t addr) {
    asm volatile("ldmatrix.sync.aligned.m8n8.x4.shared.b16 {%0,%1,%2,%3}, [%4];"
                 : "=r"(r[0]), "=r"(r[1]), "=r"(r[2]), "=r"(r[3]) : "r"(addr));
}
__device__ __forceinline__ void mma16816(float* d, const uint32_t* a, uint32_t b0, uint32_t b1) {
    asm volatile("mma.sync.aligned.m16n8k16.row.col.f32.f16.f16.f32 "
                 "{%0,%1,%2,%3}, {%4,%5,%6,%7}, {%8,%9}, {%0,%1,%2,%3};"
                 : "+f"(d[0]), "+f"(d[1]), "+f"(d[2]), "+f"(d[3])
                 : "r"(a[0]), "r"(a[1]), "r"(a[2]), "r"(a[3]), "r"(b0), "r"(b1));
}
__device__ __forceinline__ void cp_async16(uint32_t dst, const void* src) {
    asm volatile("cp.async.cg.shared.global [%0], [%1], 16;" :: "r"(dst), "l"(src));
}
__device__ __forceinline__ void cp_commit()  { asm volatile("cp.async.commit_group;"); }
__device__ __forceinline__ void cp_waitall() { asm volatile("cp.async.wait_group 0;" ::: "memory"); }
__device__ __forceinline__ void sts16(uint32_t addr, unsigned short v) {
    asm volatile("st.shared.u16 [%0], %1;" :: "r"(addr), "h"(v));
}

// ---------------- weight prepack (+ zero sums folded in) ----------------
// W = hi(fp16) + lo(fp16): captures ~22 mantissa bits -> W effectively exact.
__global__ void prepack_kernel(const float* __restrict__ w) {
    int idx = blockIdx.x * blockDim.x + threadIdx.x;   // (co*CI + ci)*9 + t
    if (idx < NN*CO) { g_sum[idx] = 0.0f; g_sq[idx] = 0.0f; }
    if (idx >= CO*CI*NTAP) return;
    int t  = idx % 9;
    int ci = (idx / 9) % CI;
    int co = idx / (9*CI);
    float v = w[idx];
    __half hi = __float2half(v);
    __half lo = __float2half(v - __half2float(hi));
    int chunk = ci >> 6, cil = ci & 63;
    int img = chunk*NTAP + t;
    uint32_t off = swz128((uint32_t)co*128 + (uint32_t)cil*2);
    *(__half*)(g_wpack + (size_t)img*32768 + off)         = hi;
    *(__half*)(g_wpack + (size_t)img*32768 + 16384 + off) = lo;
}

// ---------------- conv: implicit GEMM via mma.sync fp16 (2-pass W hi/lo) ----------------
// 512 threads = 16 warps. CTA: 128 co x 256 pixels (2 output rows).
// Warp tile: 32 co x 64 pixels (2 x 8 mma tiles).
__global__ __launch_bounds__(CONV_THREADS, 1)
void conv_mma_kernel(const float* __restrict__ x, const float* __restrict__ bias)
{
    extern __shared__ __align__(1024) unsigned char smem[];
    const uint32_t sbase = smem_u32(smem);
    const int tid    = threadIdx.x;
    const int lane   = tid & 31;
    const int w      = tid >> 5;       // 0..15
    const int warp_m = w >> 2;         // 0..3 : 32 co each
    const int warp_n = w & 3;          // 0..3 : 64 pixels each
    const int hrow   = warp_n >> 1;    // output row within CTA (0/1)
    const int colb   = (warp_n & 1) * 64;

    const int n  = blockIdx.x >> 6;             // image
    const int r0 = (blockIdx.x & 63) * ROWS_PER_CTA;

    const int mtx   = lane >> 3;       // ldmatrix matrix id this lane addresses
    const int rowin = lane & 7;

    // A ldmatrix per-thread constants (row = co, k-contiguous 128B rows, SW128)
    const uint32_t kca = (uint32_t)((mtx >> 1) * 16);
    uint32_t aoff[2], axr[2];
    #pragma unroll
    for (int mt = 0; mt < 2; mt++) {
        int co = warp_m*32 + mt*16 + (mtx & 1)*8 + rowin;
        aoff[mt] = (uint32_t)co * 128;
        axr[mt]  = (uint32_t)(co & 7) << 4;
    }
    const uint32_t kcb = (uint32_t)((mtx & 1) * 16);

    float acc[2][8][4];
    #pragma unroll
    for (int mt = 0; mt < 2; mt++)
        #pragma unroll
        for (int nt = 0; nt < 8; nt++)
            #pragma unroll
            for (int i = 0; i < 4; i++)
                acc[mt][nt][i] = 0.0f;

    // prologue: async-load A stage 0 (32KB = 2048 uint4, 512 threads x 4)
    {
        const uint4* src = (const uint4*)g_wpack;
        #pragma unroll
        for (int j = 0; j < 4; j++)
            cp_async16(sbase + (uint32_t)(tid + j*CONV_THREADS)*16, src + tid + j*CONV_THREADS);
        cp_commit();
    }

    for (int s = 0; s < NSTAGE; s++) {
        const int chunk = s / NTAP;
        const int tap   = s - chunk*NTAP;

        if (tap == 0) {
            __syncthreads();   // all warps done reading previous chunk's B
            const int cb = chunk * KC;
            for (int u = w; u < BROWS*KC; u += 16) {
                const int rho = u >> 6;          // 0..3
                const int cil = u & 63;
                const int gr  = r0 - 1 + rho;
                const float* xp = x + (((size_t)n*CI + (cb + cil)) * HH + gr) * WW;
                const bool rok = (gr >= 0) & (gr < HH);
                #pragma unroll
                for (int c0 = 0; c0 < 160; c0 += 32) {
                    const int cc = c0 + lane;
                    if (cc < BCOLS) {
                        const int gc = cc - 1;
                        float v = (rok && gc >= 0 && gc < WW) ? __ldg(xp + gc) : 0.0f;
                        __half h = __float2half(v);
                        const uint32_t off = swz128((uint32_t)(rho*BCOLS + cc)*128 + (uint32_t)cil*2);
                        sts16(sbase + SMEM_B + off, *(unsigned short*)&h);
                    }
                }
            }
        }

        cp_waitall();          // A[s] landed
        __syncthreads();       // A[s] + B visible; prior compute finished

        if (s + 1 < NSTAGE) {  // prefetch A[s+1] into the other buffer
            const uint4* src = (const uint4*)(g_wpack + (size_t)(s+1)*32768);
            const uint32_t dst = sbase + (uint32_t)((s+1) & 1) * SMEM_ABUF;
            #pragma unroll
            for (int j = 0; j < 4; j++)
                cp_async16(dst + (uint32_t)(tid + j*CONV_THREADS)*16, src + tid + j*CONV_THREADS);
            cp_commit();
        }

        // ---- compute stage s ----
        const uint32_t a_hi = sbase + (uint32_t)(s & 1) * SMEM_ABUF;
        const int kh = tap / 3, kw = tap - kh*3;
        uint32_t boff[4], bxr[4];
        #pragma unroll
        for (int p = 0; p < 4; p++) {
            int pix = (hrow + kh)*BCOLS + colb + p*16 + (mtx >> 1)*8 + rowin + kw;
            boff[p] = (uint32_t)pix * 128;
            bxr[p]  = (uint32_t)(pix & 7) << 4;
        }

        #pragma unroll
        for (int ks = 0; ks < 4; ks++) {
            uint32_t ah[2][4], al[2][4];
            #pragma unroll
            for (int mt = 0; mt < 2; mt++) {
                const uint32_t ka = (uint32_t)ks*32 + kca;
                const uint32_t ad = a_hi + aoff[mt] + (ka ^ axr[mt]);
                ldsm4(ah[mt], ad);
                ldsm4(al[mt], ad + 16384);
            }
            #pragma unroll
            for (int p = 0; p < 4; p++) {
                uint32_t bh[4];
                const uint32_t kb = (uint32_t)ks*32 + kcb;
                const uint32_t bd = sbase + SMEM_B + boff[p] + (kb ^ bxr[p]);
                ldsm4(bh, bd);
                #pragma unroll
                for (int mt = 0; mt < 2; mt++)
                    #pragma unroll
                    for (int q = 0; q < 2; q++) {
                        float* a4 = acc[mt][p*2 + q];
                        mma16816(a4, ah[mt], bh[q*2], bh[q*2+1]);  // W_hi * x
                        mma16816(a4, al[mt], bh[q*2], bh[q*2+1]);  // W_lo * x
                    }
            }
        }
    }

    // ---- epilogue: bias + store + instance sums ----
    const int g  = lane >> 2;
    const int tg = lane & 3;
    const int row = r0 + hrow;
    #pragma unroll
    for (int mt = 0; mt < 2; mt++) {
        const int co0 = warp_m*32 + mt*16 + g;
        const int co1 = co0 + 8;
        const float b0 = __ldg(bias + co0);
        const float b1 = __ldg(bias + co1);
        float* yp0 = g_y + ((size_t)(n*CO + co0) * HH + row) * WW;
        float* yp1 = g_y + ((size_t)(n*CO + co1) * HH + row) * WW;
        float s0 = 0.f, q0 = 0.f, s1 = 0.f, q1 = 0.f;
        #pragma unroll
        for (int nt = 0; nt < 8; nt++) {
            const int pix = colb + nt*8 + 2*tg;
            float v0 = acc[mt][nt][0] + b0;
            float v1 = acc[mt][nt][1] + b0;
            float v2 = acc[mt][nt][2] + b1;
            float v3 = acc[mt][nt][3] + b1;
            float2 o0 = {v0, v1}, o1 = {v2, v3};
            *(float2*)(yp0 + pix) = o0;
            *(float2*)(yp1 + pix) = o1;
            s0 += v0 + v1;  q0 += v0*v0 + v1*v1;
            s1 += v2 + v3;  q1 += v2*v2 + v3*v3;
        }
        #pragma unroll
        for (int o = 1; o <= 2; o <<= 1) {
            s0 += __shfl_xor_sync(0xffffffffu, s0, o);
            q0 += __shfl_xor_sync(0xffffffffu, q0, o);
            s1 += __shfl_xor_sync(0xffffffffu, s1, o);
            q1 += __shfl_xor_sync(0xffffffffu, q1, o);
        }
        if (tg == 0) {
            atomicAdd(&g_sum[n*CO + co0], s0);
            atomicAdd(&g_sq [n*CO + co0], q0);
            atomicAdd(&g_sum[n*CO + co1], s1);
            atomicAdd(&g_sq [n*CO + co1], q1);
        }
    }
}

// ---------------- normalize + affine + ReLU ----------------
__global__ __launch_bounds__(256)
void norm_kernel(const float* __restrict__ gamma, const float* __restrict__ beta,
                 float* __restrict__ out)
{
    const int inst = blockIdx.x;
    const int c = inst & (CO - 1);
    const float mean = g_sum[inst] * (1.0f / HWSZ);
    const float var  = g_sq[inst] * (1.0f / HWSZ) - mean * mean;
    const float rstd = rsqrtf(var + EPS);
    const float sc = rstd * gamma[c];
    const float sh = beta[c] - mean * sc;

    const float4* yp = (const float4*)(g_y + (size_t)inst * HWSZ);
    float4* op = (float4*)(out + (size_t)inst * HWSZ);
    for (int i = threadIdx.x; i < HWSZ/4; i += 256) {
        float4 v = yp[i];
        float4 o;
        o.x = fmaxf(fmaf(v.x, sc, sh), 0.0f);
        o.y = fmaxf(fmaf(v.y, sc, sh), 0.0f);
        o.z = fmaxf(fmaf(v.z, sc, sh), 0.0f);
        o.w = fmaxf(fmaf(v.w, sc, sh), 0.0f);
        op[i] = o;
    }
}

extern "C" void kernel_launch(void* const* d_in, const int* in_sizes, int n_in,
                              void* d_out, int out_size)
{
    const float* x      = (const float*)d_in[0];
    const float* weight = (const float*)d_in[1];
    const float* bias   = (const float*)d_in[2];
    const float* gamma  = (const float*)d_in[3];
    const float* beta   = (const float*)d_in[4];
    float* out = (float*)d_out;

    cudaFuncSetAttribute(conv_mma_kernel, cudaFuncAttributeMaxDynamicSharedMemorySize, SMEM_TOTAL);

    prepack_kernel<<<(CO*CI*NTAP + 255)/256, 256>>>(weight);
    conv_mma_kernel<<<NN*(HH/ROWS_PER_CTA), CONV_THREADS, SMEM_TOTAL>>>(x, bias);
    norm_kernel<<<NN*CO, 256>>>(gamma, beta, out);
}

// round 10
// speedup vs baseline: 1.9753x; 1.3852x over previous
#include <cuda_runtime.h>
#include <cuda_fp16.h>
#include <math.h>
#include <stdint.h>

#define NN 8
#define CI 128
#define CO 128
#define HH 128
#define WW 128
#define HWSZ (HH*WW)
#define EPS 1e-5f

#define KC 64                  // ci per chunk
#define NCHUNK 2
#define NTAP 9
#define NSTAGE (NCHUNK*NTAP)   // 18
#define ROWS_PER_CTA 2
#define BROWS 4                // input rows (2 output rows + halo)
#define BCOLS 130              // 128 + 2 halo
#define BPIX (BROWS*BCOLS)     // 520

#define CONV_THREADS 512       // 16 warps

// smem layout (bytes): A double buffer (16K each), then B (fp16, single)
#define SMEM_ABUF   16384
#define SMEM_B      32768
#define SMEM_B_SZ   (BPIX*128)            // 66560
#define SMEM_TOTAL  (SMEM_B + SMEM_B_SZ)  // 99328

// scratch
__device__ float g_y[(size_t)NN*CO*HH*WW];
__device__ float g_sum[NN*CO];
__device__ float g_sq[NN*CO];
__device__ unsigned char g_wpack[NSTAGE*16384];  // [chunk*9+tap]: swizzled [co][ci] fp16

// ---------------- helpers ----------------
__device__ __forceinline__ uint32_t smem_u32(const void* p) {
    uint32_t a;
    asm("{ .reg .u64 t; cvta.to.shared.u64 t, %1; cvt.u32.u64 %0, t; }" : "=r"(a) : "l"(p));
    return a;
}
__host__ __device__ __forceinline__ uint32_t swz128(uint32_t off) { return off ^ ((off >> 3) & 0x70); }

__device__ __forceinline__ void ldsm4(uint32_t* r, uint32_t addr) {
    asm volatile("ldmatrix.sync.aligned.m8n8.x4.shared.b16 {%0,%1,%2,%3}, [%4];"
                 : "=r"(r[0]), "=r"(r[1]), "=r"(r[2]), "=r"(r[3]) : "r"(addr));
}
__device__ __forceinline__ void mma16816(float* d, const uint32_t* a, uint32_t b0, uint32_t b1) {
    asm volatile("mma.sync.aligned.m16n8k16.row.col.f32.f16.f16.f32 "
                 "{%0,%1,%2,%3}, {%4,%5,%6,%7}, {%8,%9}, {%0,%1,%2,%3};"
                 : "+f"(d[0]), "+f"(d[1]), "+f"(d[2]), "+f"(d[3])
                 : "r"(a[0]), "r"(a[1]), "r"(a[2]), "r"(a[3]), "r"(b0), "r"(b1));
}
__device__ __forceinline__ void cp_async16(uint32_t dst, const void* src) {
    asm volatile("cp.async.cg.shared.global [%0], [%1], 16;" :: "r"(dst), "l"(src));
}
__device__ __forceinline__ void cp_commit()  { asm volatile("cp.async.commit_group;"); }
__device__ __forceinline__ void cp_waitall() { asm volatile("cp.async.wait_group 0;" ::: "memory"); }
__device__ __forceinline__ void sts16(uint32_t addr, unsigned short v) {
    asm volatile("st.shared.u16 [%0], %1;" :: "r"(addr), "h"(v));
}

// ---------------- weight prepack (+ zero sums folded in) ----------------
__global__ void prepack_kernel(const float* __restrict__ w) {
    int idx = blockIdx.x * blockDim.x + threadIdx.x;   // (co*CI + ci)*9 + t
    if (idx < NN*CO) { g_sum[idx] = 0.0f; g_sq[idx] = 0.0f; }
    if (idx >= CO*CI*NTAP) return;
    int t  = idx % 9;
    int ci = (idx / 9) % CI;
    int co = idx / (9*CI);
    float v = w[idx];
    __half hi = __float2half(v);
    int chunk = ci >> 6, cil = ci & 63;
    int img = chunk*NTAP + t;
    uint32_t off = swz128((uint32_t)co*128 + (uint32_t)cil*2);
    *(__half*)(g_wpack + (size_t)img*16384 + off) = hi;
}

// ---------------- conv: implicit GEMM via mma.sync fp16 (single pass) ----------------
// 512 threads = 16 warps. CTA: 128 co x 256 pixels (2 output rows).
// Warp tile: 32 co x 64 pixels (2 x 8 mma tiles).
__global__ __launch_bounds__(CONV_THREADS, 1)
void conv_mma_kernel(const float* __restrict__ x, const float* __restrict__ bias)
{
    extern __shared__ __align__(1024) unsigned char smem[];
    const uint32_t sbase = smem_u32(smem);
    const int tid    = threadIdx.x;
    const int lane   = tid & 31;
    const int w      = tid >> 5;       // 0..15
    const int warp_m = w >> 2;         // 0..3 : 32 co each
    const int warp_n = w & 3;          // 0..3 : 64 pixels each
    const int hrow   = warp_n >> 1;    // output row within CTA (0/1)
    const int colb   = (warp_n & 1) * 64;

    const int n  = blockIdx.x >> 6;             // image
    const int r0 = (blockIdx.x & 63) * ROWS_PER_CTA;

    const int mtx   = lane >> 3;       // ldmatrix matrix id this lane addresses
    const int rowin = lane & 7;

    // A ldmatrix per-thread constants (row = co, k-contiguous 128B rows, SW128)
    const uint32_t kca = (uint32_t)((mtx >> 1) * 16);
    uint32_t aoff[2], axr[2];
    #pragma unroll
    for (int mt = 0; mt < 2; mt++) {
        int co = warp_m*32 + mt*16 + (mtx & 1)*8 + rowin;
        aoff[mt] = (uint32_t)co * 128;
        axr[mt]  = (uint32_t)(co & 7) << 4;
    }
    const uint32_t kcb = (uint32_t)((mtx & 1) * 16);

    float acc[2][8][4];
    #pragma unroll
    for (int mt = 0; mt < 2; mt++)
        #pragma unroll
        for (int nt = 0; nt < 8; nt++)
            #pragma unroll
            for (int i = 0; i < 4; i++)
                acc[mt][nt][i] = 0.0f;

    // prologue: async-load A stage 0 (16KB = 1024 uint4, 512 threads x 2)
    {
        const uint4* src = (const uint4*)g_wpack;
        #pragma unroll
        for (int j = 0; j < 2; j++)
            cp_async16(sbase + (uint32_t)(tid + j*CONV_THREADS)*16, src + tid + j*CONV_THREADS);
        cp_commit();
    }

    for (int s = 0; s < NSTAGE; s++) {
        const int chunk = s / NTAP;
        const int tap   = s - chunk*NTAP;

        if (tap == 0) {
            __syncthreads();   // all warps done reading previous chunk's B
            const int cb = chunk * KC;
            for (int u = w; u < BROWS*KC; u += 16) {
                const int rho = u >> 6;          // 0..3
                const int cil = u & 63;
                const int gr  = r0 - 1 + rho;
                const float* xp = x + (((size_t)n*CI + (cb + cil)) * HH + gr) * WW;
                const bool rok = (gr >= 0) & (gr < HH);
                #pragma unroll
                for (int c0 = 0; c0 < 160; c0 += 32) {
                    const int cc = c0 + lane;
                    if (cc < BCOLS) {
                        const int gc = cc - 1;
                        float v = (rok && gc >= 0 && gc < WW) ? __ldg(xp + gc) : 0.0f;
                        __half h = __float2half(v);
                        const uint32_t off = swz128((uint32_t)(rho*BCOLS + cc)*128 + (uint32_t)cil*2);
                        sts16(sbase + SMEM_B + off, *(unsigned short*)&h);
                    }
                }
            }
        }

        cp_waitall();          // A[s] landed
        __syncthreads();       // A[s] + B visible; prior compute finished

        if (s + 1 < NSTAGE) {  // prefetch A[s+1] into the other buffer
            const uint4* src = (const uint4*)(g_wpack + (size_t)(s+1)*16384);
            const uint32_t dst = sbase + (uint32_t)((s+1) & 1) * SMEM_ABUF;
            #pragma unroll
            for (int j = 0; j < 2; j++)
                cp_async16(dst + (uint32_t)(tid + j*CONV_THREADS)*16, src + tid + j*CONV_THREADS);
            cp_commit();
        }

        // ---- compute stage s ----
        const uint32_t a_base = sbase + (uint32_t)(s & 1) * SMEM_ABUF;
        const int kh = tap / 3, kw = tap - kh*3;
        uint32_t boff[4], bxr[4];
        #pragma unroll
        for (int p = 0; p < 4; p++) {
            int pix = (hrow + kh)*BCOLS + colb + p*16 + (mtx >> 1)*8 + rowin + kw;
            boff[p] = (uint32_t)pix * 128;
            bxr[p]  = (uint32_t)(pix & 7) << 4;
        }

        #pragma unroll
        for (int ks = 0; ks < 4; ks++) {
            uint32_t ah[2][4];
            #pragma unroll
            for (int mt = 0; mt < 2; mt++) {
                const uint32_t ka = (uint32_t)ks*32 + kca;
                const uint32_t ad = a_base + aoff[mt] + (ka ^ axr[mt]);
                ldsm4(ah[mt], ad);
            }
            #pragma unroll
            for (int p = 0; p < 4; p++) {
                uint32_t bh[4];
                const uint32_t kb = (uint32_t)ks*32 + kcb;
                const uint32_t bd = sbase + SMEM_B + boff[p] + (kb ^ bxr[p]);
                ldsm4(bh, bd);
                #pragma unroll
                for (int mt = 0; mt < 2; mt++)
                    #pragma unroll
                    for (int q = 0; q < 2; q++) {
                        float* a4 = acc[mt][p*2 + q];
                        mma16816(a4, ah[mt], bh[q*2], bh[q*2+1]);
                    }
            }
        }
    }

    // ---- epilogue: bias + store + instance sums ----
    const int g  = lane >> 2;
    const int tg = lane & 3;
    const int row = r0 + hrow;
    #pragma unroll
    for (int mt = 0; mt < 2; mt++) {
        const int co0 = warp_m*32 + mt*16 + g;
        const int co1 = co0 + 8;
        const float b0 = __ldg(bias + co0);
        const float b1 = __ldg(bias + co1);
        float* yp0 = g_y + ((size_t)(n*CO + co0) * HH + row) * WW;
        float* yp1 = g_y + ((size_t)(n*CO + co1) * HH + row) * WW;
        float s0 = 0.f, q0 = 0.f, s1 = 0.f, q1 = 0.f;
        #pragma unroll
        for (int nt = 0; nt < 8; nt++) {
            const int pix = colb + nt*8 + 2*tg;
            float v0 = acc[mt][nt][0] + b0;
            float v1 = acc[mt][nt][1] + b0;
            float v2 = acc[mt][nt][2] + b1;
            float v3 = acc[mt][nt][3] + b1;
            float2 o0 = {v0, v1}, o1 = {v2, v3};
            *(float2*)(yp0 + pix) = o0;
            *(float2*)(yp1 + pix) = o1;
            s0 += v0 + v1;  q0 += v0*v0 + v1*v1;
            s1 += v2 + v3;  q1 += v2*v2 + v3*v3;
        }
        #pragma unroll
        for (int o = 1; o <= 2; o <<= 1) {
            s0 += __shfl_xor_sync(0xffffffffu, s0, o);
            q0 += __shfl_xor_sync(0xffffffffu, q0, o);
            s1 += __shfl_xor_sync(0xffffffffu, s1, o);
            q1 += __shfl_xor_sync(0xffffffffu, q1, o);
        }
        if (tg == 0) {
            atomicAdd(&g_sum[n*CO + co0], s0);
            atomicAdd(&g_sq [n*CO + co0], q0);
            atomicAdd(&g_sum[n*CO + co1], s1);
            atomicAdd(&g_sq [n*CO + co1], q1);
        }
    }
}

// ---------------- normalize + affine + ReLU ----------------
__global__ __launch_bounds__(256)
void norm_kernel(const float* __restrict__ gamma, const float* __restrict__ beta,
                 float* __restrict__ out)
{
    const int inst = blockIdx.x;
    const int c = inst & (CO - 1);
    const float mean = g_sum[inst] * (1.0f / HWSZ);
    const float var  = g_sq[inst] * (1.0f / HWSZ) - mean * mean;
    const float rstd = rsqrtf(var + EPS);
    const float sc = rstd * gamma[c];
    const float sh = beta[c] - mean * sc;

    const float4* yp = (const float4*)(g_y + (size_t)inst * HWSZ);
    float4* op = (float4*)(out + (size_t)inst * HWSZ);
    for (int i = threadIdx.x; i < HWSZ/4; i += 256) {
        float4 v = yp[i];
        float4 o;
        o.x = fmaxf(fmaf(v.x, sc, sh), 0.0f);
        o.y = fmaxf(fmaf(v.y, sc, sh), 0.0f);
        o.z = fmaxf(fmaf(v.z, sc, sh), 0.0f);
        o.w = fmaxf(fmaf(v.w, sc, sh), 0.0f);
        op[i] = o;
    }
}

extern "C" void kernel_launch(void* const* d_in, const int* in_sizes, int n_in,
                              void* d_out, int out_size)
{
    const float* x      = (const float*)d_in[0];
    const float* weight = (const float*)d_in[1];
    const float* bias   = (const float*)d_in[2];
    const float* gamma  = (const float*)d_in[3];
    const float* beta   = (const float*)d_in[4];
    float* out = (float*)d_out;

    cudaFuncSetAttribute(conv_mma_kernel, cudaFuncAttributeMaxDynamicSharedMemorySize, SMEM_TOTAL);

    prepack_kernel<<<(CO*CI*NTAP + 255)/256, 256>>>(weight);
    conv_mma_kernel<<<NN*(HH/ROWS_PER_CTA), CONV_THREADS, SMEM_TOTAL>>>(x, bias);
    norm_kernel<<<NN*CO, 256>>>(gamma, beta, out);
}

// round 11
// speedup vs baseline: 2.2629x; 1.1456x over previous
#include <cuda_runtime.h>
#include <cuda_fp16.h>
#include <math.h>
#include <stdint.h>

#define NN 8
#define CI 128
#define CO 128
#define HH 128
#define WW 128
#define HWSZ (HH*WW)
#define EPS 1e-5f

#define KC 64                  // ci per chunk
#define NCHUNK 2
#define NTAP 9
#define NSTAGE (NCHUNK*NTAP)   // 18
#define ROWS_PER_CTA 2
#define BROWS 4                // input rows (2 output rows + halo)
#define BCOLS 130              // 128 + 2 halo
#define BPIX (BROWS*BCOLS)     // 520

#define CONV_THREADS 512       // 16 warps

// smem layout (bytes): A triple buffer (16K each), then B chunk0 + chunk1 resident
#define SMEM_B      49152
#define SMEM_B_SZ   (BPIX*128)            // 66560 per chunk
#define SMEM_TOTAL  (SMEM_B + 2*SMEM_B_SZ)  // 182272

// scratch
__device__ float g_y[(size_t)NN*CO*HH*WW];
__device__ float g_sum[NN*CO];
__device__ float g_sq[NN*CO];
__device__ unsigned char g_wpack[NSTAGE*16384];       // [chunk*9+tap]: swizzled [co][ci] fp16
__device__ __half g_xt[(size_t)NN*130*130*128];       // channel-last fp16 x, halo-padded (rows/cols 0 and 129 = 0)

// ---------------- helpers ----------------
__device__ __forceinline__ uint32_t smem_u32(const void* p) {
    uint32_t a;
    asm("{ .reg .u64 t; cvta.to.shared.u64 t, %1; cvt.u32.u64 %0, t; }" : "=r"(a) : "l"(p));
    return a;
}
__host__ __device__ __forceinline__ uint32_t swz128(uint32_t off) { return off ^ ((off >> 3) & 0x70); }

__device__ __forceinline__ void ldsm4(uint32_t* r, uint32_t addr) {
    asm volatile("ldmatrix.sync.aligned.m8n8.x4.shared.b16 {%0,%1,%2,%3}, [%4];"
                 : "=r"(r[0]), "=r"(r[1]), "=r"(r[2]), "=r"(r[3]) : "r"(addr));
}
__device__ __forceinline__ void mma16816(float* d, const uint32_t* a, uint32_t b0, uint32_t b1) {
    asm volatile("mma.sync.aligned.m16n8k16.row.col.f32.f16.f16.f32 "
                 "{%0,%1,%2,%3}, {%4,%5,%6,%7}, {%8,%9}, {%0,%1,%2,%3};"
                 : "+f"(d[0]), "+f"(d[1]), "+f"(d[2]), "+f"(d[3])
                 : "r"(a[0]), "r"(a[1]), "r"(a[2]), "r"(a[3]), "r"(b0), "r"(b1));
}
__device__ __forceinline__ void cp_async16(uint32_t dst, const void* src) {
    asm volatile("cp.async.cg.shared.global [%0], [%1], 16;" :: "r"(dst), "l"(src));
}
__device__ __forceinline__ void cp_commit()  { asm volatile("cp.async.commit_group;"); }
__device__ __forceinline__ void cp_wait1()   { asm volatile("cp.async.wait_group 1;" ::: "memory"); }
__device__ __forceinline__ void cp_waitall() { asm volatile("cp.async.wait_group 0;" ::: "memory"); }

// ---------------- x transpose to channel-last fp16 with halo pad ----------------
// x_t[n][r 0..129][c 0..129][ci 0..127]; r/c index = spatial+1; borders zero.
__global__ __launch_bounds__(256)
void xt_kernel(const float* __restrict__ x)
{
    __shared__ __half s_t[128*130];   // [gc][ci] with ci-row padded to 130
    const int row = blockIdx.x;       // 0..129
    const int n   = blockIdx.y;
    const int tid = threadIdx.x;
    __half* outr = g_xt + (size_t)(n*130 + row)*130*128;

    if (row == 0 || row == 129) {
        const uint4 z = {0,0,0,0};
        for (int i = tid; i < 130*128/8; i += 256) ((uint4*)outr)[i] = z;
        return;
    }
    const int gr = row - 1;
    const float* xp = x + ((size_t)n*CI*HH + gr)*WW;
    for (int idx = tid; idx < 128*128; idx += 256) {
        const int ci = idx >> 7, gc = idx & 127;
        s_t[gc*130 + ci] = __float2half(xp[(size_t)ci*HWSZ + gc]);
    }
    __syncthreads();
    for (int idx = tid; idx < 128*16; idx += 256) {
        const int gc = idx >> 4, c8 = (idx & 15) * 8;
        __half tmp[8];
        #pragma unroll
        for (int j = 0; j < 8; j++) tmp[j] = s_t[gc*130 + c8 + j];
        *(uint4*)(outr + (size_t)(gc+1)*128 + c8) = *(uint4*)tmp;
    }
    // zero pad columns 0 and 129
    if (tid < 32) {
        const uint4 z = {0,0,0,0};
        if (tid < 16) ((uint4*)(outr))[tid] = z;
        else          ((uint4*)(outr + (size_t)129*128))[tid-16] = z;
    }
}

// ---------------- weight prepack (+ zero sums folded in) ----------------
__global__ void prepack_kernel(const float* __restrict__ w) {
    int idx = blockIdx.x * blockDim.x + threadIdx.x;   // (co*CI + ci)*9 + t
    if (idx < NN*CO) { g_sum[idx] = 0.0f; g_sq[idx] = 0.0f; }
    if (idx >= CO*CI*NTAP) return;
    int t  = idx % 9;
    int ci = (idx / 9) % CI;
    int co = idx / (9*CI);
    __half hi = __float2half(w[idx]);
    int chunk = ci >> 6, cil = ci & 63;
    int img = chunk*NTAP + t;
    uint32_t off = swz128((uint32_t)co*128 + (uint32_t)cil*2);
    *(__half*)(g_wpack + (size_t)img*16384 + off) = hi;
}

// ---------------- conv: implicit GEMM via mma.sync fp16, full cp.async pipeline ----------------
// 512 threads = 16 warps. CTA: 128 co x 256 pixels (2 output rows).
// Warp tile: 32 co x 64 pixels (2 x 8 mma tiles).
__global__ __launch_bounds__(CONV_THREADS, 1)
void conv_mma_kernel(const float* __restrict__ dummy, const float* __restrict__ bias)
{
    extern __shared__ __align__(1024) unsigned char smem[];
    const uint32_t sbase = smem_u32(smem);
    const int tid    = threadIdx.x;
    const int lane   = tid & 31;
    const int w      = tid >> 5;       // 0..15
    const int warp_m = w >> 2;         // 0..3 : 32 co each
    const int warp_n = w & 3;          // 0..3 : 64 pixels each
    const int hrow   = warp_n >> 1;    // output row within CTA (0/1)
    const int colb   = (warp_n & 1) * 64;

    const int n  = blockIdx.x >> 6;             // image
    const int r0 = (blockIdx.x & 63) * ROWS_PER_CTA;

    const int mtx   = lane >> 3;
    const int rowin = lane & 7;

    const uint32_t kca = (uint32_t)((mtx >> 1) * 16);
    uint32_t aoff[2], axr[2];
    #pragma unroll
    for (int mt = 0; mt < 2; mt++) {
        int co = warp_m*32 + mt*16 + (mtx & 1)*8 + rowin;
        aoff[mt] = (uint32_t)co * 128;
        axr[mt]  = (uint32_t)(co & 7) << 4;
    }
    const uint32_t kcb = (uint32_t)((mtx & 1) * 16);

    float acc[2][8][4];
    #pragma unroll
    for (int mt = 0; mt < 2; mt++)
        #pragma unroll
        for (int nt = 0; nt < 8; nt++)
            #pragma unroll
            for (int i = 0; i < 4; i++)
                acc[mt][nt][i] = 0.0f;

    const __half* xtn = g_xt + (size_t)n*130*130*128;

    // prologue: B chunk0 (group 0), A stage0 (group 1)
    for (int u = tid; u < BPIX*8; u += CONV_THREADS) {
        const int pix = u >> 3, j = u & 7;
        const int rho = pix / BCOLS, oc = pix - rho*BCOLS;
        const char* src = (const char*)(xtn + ((size_t)(r0 + rho)*130 + oc)*128) + j*16;
        cp_async16(sbase + SMEM_B + swz128((uint32_t)pix*128 + j*16), src);
    }
    cp_commit();
    {
        const uint4* src = (const uint4*)g_wpack;
        cp_async16(sbase + (uint32_t)tid*16,              src + tid);
        cp_async16(sbase + (uint32_t)(tid + 512)*16,      src + tid + 512);
    }
    cp_commit();

    for (int s = 0; s < NSTAGE; s++) {
        bool issued = false;
        if (s + 1 < NSTAGE) {   // A[s+1] into triple-buffer slot (s+1)%3
            const uint4* src = (const uint4*)(g_wpack + (size_t)(s+1)*16384);
            const uint32_t dst = sbase + (uint32_t)((s+1) % 3) * 16384;
            cp_async16(dst + (uint32_t)tid*16,         src + tid);
            cp_async16(dst + (uint32_t)(tid+512)*16,   src + tid + 512);
            issued = true;
        }
        if (s < 8) {            // B chunk1 slice (520 transfers/stage, 8 stages)
            for (int u = s*520 + tid; u < (s+1)*520; u += CONV_THREADS) {
                const int pix = u >> 3, j = u & 7;
                const int rho = pix / BCOLS, oc = pix - rho*BCOLS;
                const char* src = (const char*)(xtn + ((size_t)(r0 + rho)*130 + oc)*128 + 64) + j*16;
                cp_async16(sbase + SMEM_B + SMEM_B_SZ + swz128((uint32_t)pix*128 + j*16), src);
            }
            issued = true;
        }
        if (issued) { cp_commit(); cp_wait1(); }
        else        { cp_waitall(); }
        __syncthreads();

        // ---- compute stage s ----
        const int chunk = s / NTAP;
        const int tap   = s - chunk*NTAP;
        const uint32_t a_base = sbase + (uint32_t)(s % 3) * 16384;
        const uint32_t b_base = sbase + SMEM_B + (uint32_t)chunk * SMEM_B_SZ;
        const int kh = tap / 3, kw = tap - kh*3;
        uint32_t boff[4], bxr[4];
        #pragma unroll
        for (int p = 0; p < 4; p++) {
            int pix = (hrow + kh)*BCOLS + colb + p*16 + (mtx >> 1)*8 + rowin + kw;
            boff[p] = (uint32_t)pix * 128;
            bxr[p]  = (uint32_t)(pix & 7) << 4;
        }

        #pragma unroll
        for (int ks = 0; ks < 4; ks++) {
            uint32_t ah[2][4];
            #pragma unroll
            for (int mt = 0; mt < 2; mt++) {
                const uint32_t ka = (uint32_t)ks*32 + kca;
                ldsm4(ah[mt], a_base + aoff[mt] + (ka ^ axr[mt]));
            }
            #pragma unroll
            for (int p = 0; p < 4; p++) {
                uint32_t bh[4];
                const uint32_t kb = (uint32_t)ks*32 + kcb;
                ldsm4(bh, b_base + boff[p] + (kb ^ bxr[p]));
                #pragma unroll
                for (int mt = 0; mt < 2; mt++)
                    #pragma unroll
                    for (int q = 0; q < 2; q++) {
                        float* a4 = acc[mt][p*2 + q];
                        mma16816(a4, ah[mt], bh[q*2], bh[q*2+1]);
                    }
            }
        }
    }

    // ---- epilogue: bias + store + instance sums ----
    const int g  = lane >> 2;
    const int tg = lane & 3;
    const int row = r0 + hrow;
    #pragma unroll
    for (int mt = 0; mt < 2; mt++) {
        const int co0 = warp_m*32 + mt*16 + g;
        const int co1 = co0 + 8;
        const float b0 = __ldg(bias + co0);
        const float b1 = __ldg(bias + co1);
        float* yp0 = g_y + ((size_t)(n*CO + co0) * HH + row) * WW;
        float* yp1 = g_y + ((size_t)(n*CO + co1) * HH + row) * WW;
        float s0 = 0.f, q0 = 0.f, s1 = 0.f, q1 = 0.f;
        #pragma unroll
        for (int nt = 0; nt < 8; nt++) {
            const int pix = colb + nt*8 + 2*tg;
            float v0 = acc[mt][nt][0] + b0;
            float v1 = acc[mt][nt][1] + b0;
            float v2 = acc[mt][nt][2] + b1;
            float v3 = acc[mt][nt][3] + b1;
            float2 o0 = {v0, v1}, o1 = {v2, v3};
            *(float2*)(yp0 + pix) = o0;
            *(float2*)(yp1 + pix) = o1;
            s0 += v0 + v1;  q0 += v0*v0 + v1*v1;
            s1 += v2 + v3;  q1 += v2*v2 + v3*v3;
        }
        #pragma unroll
        for (int o = 1; o <= 2; o <<= 1) {
            s0 += __shfl_xor_sync(0xffffffffu, s0, o);
            q0 += __shfl_xor_sync(0xffffffffu, q0, o);
            s1 += __shfl_xor_sync(0xffffffffu, s1, o);
            q1 += __shfl_xor_sync(0xffffffffu, q1, o);
        }
        if (tg == 0) {
            atomicAdd(&g_sum[n*CO + co0], s0);
            atomicAdd(&g_sq [n*CO + co0], q0);
            atomicAdd(&g_sum[n*CO + co1], s1);
            atomicAdd(&g_sq [n*CO + co1], q1);
        }
    }
}

// ---------------- normalize + affine + ReLU ----------------
__global__ __launch_bounds__(256)
void norm_kernel(const float* __restrict__ gamma, const float* __restrict__ beta,
                 float* __restrict__ out)
{
    const int inst = blockIdx.x;
    const int c = inst & (CO - 1);
    const float mean = g_sum[inst] * (1.0f / HWSZ);
    const float var  = g_sq[inst] * (1.0f / HWSZ) - mean * mean;
    const float rstd = rsqrtf(var + EPS);
    const float sc = rstd * gamma[c];
    const float sh = beta[c] - mean * sc;

    const float4* yp = (const float4*)(g_y + (size_t)inst * HWSZ);
    float4* op = (float4*)(out + (size_t)inst * HWSZ);
    for (int i = threadIdx.x; i < HWSZ/4; i += 256) {
        float4 v = yp[i];
        float4 o;
        o.x = fmaxf(fmaf(v.x, sc, sh), 0.0f);
        o.y = fmaxf(fmaf(v.y, sc, sh), 0.0f);
        o.z = fmaxf(fmaf(v.z, sc, sh), 0.0f);
        o.w = fmaxf(fmaf(v.w, sc, sh), 0.0f);
        op[i] = o;
    }
}

extern "C" void kernel_launch(void* const* d_in, const int* in_sizes, int n_in,
                              void* d_out, int out_size)
{
    const float* x      = (const float*)d_in[0];
    const float* weight = (const float*)d_in[1];
    const float* bias   = (const float*)d_in[2];
    const float* gamma  = (const float*)d_in[3];
    const float* beta   = (const float*)d_in[4];
    float* out = (float*)d_out;

    cudaFuncSetAttribute(conv_mma_kernel, cudaFuncAttributeMaxDynamicSharedMemorySize, SMEM_TOTAL);

    xt_kernel<<<dim3(130, NN), 256>>>(x);
    prepack_kernel<<<(CO*CI*NTAP + 255)/256, 256>>>(weight);
    conv_mma_kernel<<<NN*(HH/ROWS_PER_CTA), CONV_THREADS, SMEM_TOTAL>>>(x, bias);
    norm_kernel<<<NN*CO, 256>>>(gamma, beta, out);
}

// round 12
// speedup vs baseline: 2.2839x; 1.0093x over previous
#include <cuda_runtime.h>
#include <cuda_fp16.h>
#include <math.h>
#include <stdint.h>

#define NN 8
#define CI 128
#define CO 128
#define HH 128
#define WW 128
#define HWSZ (HH*WW)
#define EPS 1e-5f

#define KC 64                  // ci per chunk
#define NCHUNK 2
#define NTAP 9
#define NSTAGE (NCHUNK*NTAP)   // 18
#define ROWS_PER_CTA 2
#define BROWS 4                // input rows (2 output rows + halo)
#define BCOLS 130              // 128 + 2 halo
#define BPIX (BROWS*BCOLS)     // 520

#define CONV_THREADS 512       // 16 warps

// smem layout (bytes): A triple buffer (16K each), then B chunk0 + chunk1 resident
#define SMEM_B      49152
#define SMEM_B_SZ   (BPIX*128)            // 66560 per chunk
#define SMEM_TOTAL  (SMEM_B + 2*SMEM_B_SZ)  // 182272

// scratch
__device__ __half g_y[(size_t)NN*CO*HH*WW];           // conv output (fp16, 32MB)
__device__ float g_sum[NN*CO];
__device__ float g_sq[NN*CO];
__device__ unsigned char g_wpack[NSTAGE*16384];       // [chunk*9+tap]: swizzled [co][ci] fp16
__device__ __half g_xt[(size_t)NN*130*130*128];       // channel-last fp16 x, halo-padded

// ---------------- helpers ----------------
__device__ __forceinline__ uint32_t smem_u32(const void* p) {
    uint32_t a;
    asm("{ .reg .u64 t; cvta.to.shared.u64 t, %1; cvt.u32.u64 %0, t; }" : "=r"(a) : "l"(p));
    return a;
}
__host__ __device__ __forceinline__ uint32_t swz128(uint32_t off) { return off ^ ((off >> 3) & 0x70); }

__device__ __forceinline__ void ldsm4(uint32_t* r, uint32_t addr) {
    asm volatile("ldmatrix.sync.aligned.m8n8.x4.shared.b16 {%0,%1,%2,%3}, [%4];"
                 : "=r"(r[0]), "=r"(r[1]), "=r"(r[2]), "=r"(r[3]) : "r"(addr));
}
__device__ __forceinline__ void mma16816(float* d, const uint32_t* a, uint32_t b0, uint32_t b1) {
    asm volatile("mma.sync.aligned.m16n8k16.row.col.f32.f16.f16.f32 "
                 "{%0,%1,%2,%3}, {%4,%5,%6,%7}, {%8,%9}, {%0,%1,%2,%3};"
                 : "+f"(d[0]), "+f"(d[1]), "+f"(d[2]), "+f"(d[3])
                 : "r"(a[0]), "r"(a[1]), "r"(a[2]), "r"(a[3]), "r"(b0), "r"(b1));
}
__device__ __forceinline__ void cp_async16(uint32_t dst, const void* src) {
    asm volatile("cp.async.cg.shared.global [%0], [%1], 16;" :: "r"(dst), "l"(src));
}
__device__ __forceinline__ void cp_commit()  { asm volatile("cp.async.commit_group;"); }
__device__ __forceinline__ void cp_wait1()   { asm volatile("cp.async.wait_group 1;" ::: "memory"); }
__device__ __forceinline__ void cp_waitall() { asm volatile("cp.async.wait_group 0;" ::: "memory"); }

// ---------------- fused preprocessing: x transpose + weight prepack ----------------
// blocks [0, 130*NN): x_t rows;  blocks [130*NN, 130*NN+576): weight prepack + sum zeroing
#define XT_BLOCKS (130*NN)
#define PP_BLOCKS ((CO*CI*NTAP + 255)/256)
__global__ __launch_bounds__(256)
void prep_kernel(const float* __restrict__ x, const float* __restrict__ w)
{
    if (blockIdx.x >= XT_BLOCKS) {
        // ---- weight prepack ----
        int idx = (blockIdx.x - XT_BLOCKS) * 256 + threadIdx.x;
        if (idx < NN*CO) { g_sum[idx] = 0.0f; g_sq[idx] = 0.0f; }
        if (idx >= CO*CI*NTAP) return;
        int t  = idx % 9;
        int ci = (idx / 9) % CI;
        int co = idx / (9*CI);
        __half hi = __float2half(w[idx]);
        int chunk = ci >> 6, cil = ci & 63;
        int img = chunk*NTAP + t;
        uint32_t off = swz128((uint32_t)co*128 + (uint32_t)cil*2);
        *(__half*)(g_wpack + (size_t)img*16384 + off) = hi;
        return;
    }
    // ---- x transpose to channel-last fp16 with halo pad ----
    __shared__ __half s_t[128*130];   // [gc][ci] padded to 130
    const int row = blockIdx.x % 130;
    const int n   = blockIdx.x / 130;
    const int tid = threadIdx.x;
    __half* outr = g_xt + (size_t)(n*130 + row)*130*128;

    if (row == 0 || row == 129) {
        const uint4 z = {0,0,0,0};
        for (int i = tid; i < 130*128/8; i += 256) ((uint4*)outr)[i] = z;
        return;
    }
    const int gr = row - 1;
    const float* xp = x + ((size_t)n*CI*HH + gr)*WW;
    for (int idx = tid; idx < 128*128; idx += 256) {
        const int ci = idx >> 7, gc = idx & 127;
        s_t[gc*130 + ci] = __float2half(xp[(size_t)ci*HWSZ + gc]);
    }
    __syncthreads();
    for (int idx = tid; idx < 128*16; idx += 256) {
        const int gc = idx >> 4, c8 = (idx & 15) * 8;
        __half tmp[8];
        #pragma unroll
        for (int j = 0; j < 8; j++) tmp[j] = s_t[gc*130 + c8 + j];
        *(uint4*)(outr + (size_t)(gc+1)*128 + c8) = *(uint4*)tmp;
    }
    if (tid < 32) {
        const uint4 z = {0,0,0,0};
        if (tid < 16) ((uint4*)(outr))[tid] = z;
        else          ((uint4*)(outr + (size_t)129*128))[tid-16] = z;
    }
}

// ---------------- conv: implicit GEMM via mma.sync fp16, full cp.async pipeline ----------------
__global__ __launch_bounds__(CONV_THREADS, 1)
void conv_mma_kernel(const float* __restrict__ bias)
{
    extern __shared__ __align__(1024) unsigned char smem[];
    const uint32_t sbase = smem_u32(smem);
    const int tid    = threadIdx.x;
    const int lane   = tid & 31;
    const int w      = tid >> 5;       // 0..15
    const int warp_m = w >> 2;         // 0..3 : 32 co each
    const int warp_n = w & 3;          // 0..3 : 64 pixels each
    const int hrow   = warp_n >> 1;
    const int colb   = (warp_n & 1) * 64;

    const int n  = blockIdx.x >> 6;
    const int r0 = (blockIdx.x & 63) * ROWS_PER_CTA;

    const int mtx   = lane >> 3;
    const int rowin = lane & 7;

    const uint32_t kca = (uint32_t)((mtx >> 1) * 16);
    uint32_t aoff[2], axr[2];
    #pragma unroll
    for (int mt = 0; mt < 2; mt++) {
        int co = warp_m*32 + mt*16 + (mtx & 1)*8 + rowin;
        aoff[mt] = (uint32_t)co * 128;
        axr[mt]  = (uint32_t)(co & 7) << 4;
    }
    const uint32_t kcb = (uint32_t)((mtx & 1) * 16);

    float acc[2][8][4];
    #pragma unroll
    for (int mt = 0; mt < 2; mt++)
        #pragma unroll
        for (int nt = 0; nt < 8; nt++)
            #pragma unroll
            for (int i = 0; i < 4; i++)
                acc[mt][nt][i] = 0.0f;

    const __half* xtn = g_xt + (size_t)n*130*130*128;

    // prologue: B chunk0 (group 0), A stage0 (group 1)
    for (int u = tid; u < BPIX*8; u += CONV_THREADS) {
        const int pix = u >> 3, j = u & 7;
        const int rho = pix / BCOLS, oc = pix - rho*BCOLS;
        const char* src = (const char*)(xtn + ((size_t)(r0 + rho)*130 + oc)*128) + j*16;
        cp_async16(sbase + SMEM_B + swz128((uint32_t)pix*128 + j*16), src);
    }
    cp_commit();
    {
        const uint4* src = (const uint4*)g_wpack;
        cp_async16(sbase + (uint32_t)tid*16,         src + tid);
        cp_async16(sbase + (uint32_t)(tid + 512)*16, src + tid + 512);
    }
    cp_commit();

    for (int s = 0; s < NSTAGE; s++) {
        bool issued = false;
        if (s + 1 < NSTAGE) {
            const uint4* src = (const uint4*)(g_wpack + (size_t)(s+1)*16384);
            const uint32_t dst = sbase + (uint32_t)((s+1) % 3) * 16384;
            cp_async16(dst + (uint32_t)tid*16,       src + tid);
            cp_async16(dst + (uint32_t)(tid+512)*16, src + tid + 512);
            issued = true;
        }
        if (s < 8) {
            for (int u = s*520 + tid; u < (s+1)*520; u += CONV_THREADS) {
                const int pix = u >> 3, j = u & 7;
                const int rho = pix / BCOLS, oc = pix - rho*BCOLS;
                const char* src = (const char*)(xtn + ((size_t)(r0 + rho)*130 + oc)*128 + 64) + j*16;
                cp_async16(sbase + SMEM_B + SMEM_B_SZ + swz128((uint32_t)pix*128 + j*16), src);
            }
            issued = true;
        }
        if (issued) { cp_commit(); cp_wait1(); }
        else        { cp_waitall(); }
        __syncthreads();

        const int chunk = s / NTAP;
        const int tap   = s - chunk*NTAP;
        const uint32_t a_base = sbase + (uint32_t)(s % 3) * 16384;
        const uint32_t b_base = sbase + SMEM_B + (uint32_t)chunk * SMEM_B_SZ;
        const int kh = tap / 3, kw = tap - kh*3;
        uint32_t boff[4], bxr[4];
        #pragma unroll
        for (int p = 0; p < 4; p++) {
            int pix = (hrow + kh)*BCOLS + colb + p*16 + (mtx >> 1)*8 + rowin + kw;
            boff[p] = (uint32_t)pix * 128;
            bxr[p]  = (uint32_t)(pix & 7) << 4;
        }

        #pragma unroll
        for (int ks = 0; ks < 4; ks++) {
            uint32_t ah[2][4];
            #pragma unroll
            for (int mt = 0; mt < 2; mt++) {
                const uint32_t ka = (uint32_t)ks*32 + kca;
                ldsm4(ah[mt], a_base + aoff[mt] + (ka ^ axr[mt]));
            }
            #pragma unroll
            for (int p = 0; p < 4; p++) {
                uint32_t bh[4];
                const uint32_t kb = (uint32_t)ks*32 + kcb;
                ldsm4(bh, b_base + boff[p] + (kb ^ bxr[p]));
                #pragma unroll
                for (int mt = 0; mt < 2; mt++)
                    #pragma unroll
                    for (int q = 0; q < 2; q++) {
                        float* a4 = acc[mt][p*2 + q];
                        mma16816(a4, ah[mt], bh[q*2], bh[q*2+1]);
                    }
            }
        }
    }

    // ---- epilogue: bias + fp16 store + instance sums (fp32) ----
    const int g  = lane >> 2;
    const int tg = lane & 3;
    const int row = r0 + hrow;
    #pragma unroll
    for (int mt = 0; mt < 2; mt++) {
        const int co0 = warp_m*32 + mt*16 + g;
        const int co1 = co0 + 8;
        const float b0 = __ldg(bias + co0);
        const float b1 = __ldg(bias + co1);
        __half* yp0 = g_y + ((size_t)(n*CO + co0) * HH + row) * WW;
        __half* yp1 = g_y + ((size_t)(n*CO + co1) * HH + row) * WW;
        float s0 = 0.f, q0 = 0.f, s1 = 0.f, q1 = 0.f;
        #pragma unroll
        for (int nt = 0; nt < 8; nt++) {
            const int pix = colb + nt*8 + 2*tg;
            float v0 = acc[mt][nt][0] + b0;
            float v1 = acc[mt][nt][1] + b0;
            float v2 = acc[mt][nt][2] + b1;
            float v3 = acc[mt][nt][3] + b1;
            *(__half2*)(yp0 + pix) = __floats2half2_rn(v0, v1);
            *(__half2*)(yp1 + pix) = __floats2half2_rn(v2, v3);
            s0 += v0 + v1;  q0 += v0*v0 + v1*v1;
            s1 += v2 + v3;  q1 += v2*v2 + v3*v3;
        }
        #pragma unroll
        for (int o = 1; o <= 2; o <<= 1) {
            s0 += __shfl_xor_sync(0xffffffffu, s0, o);
            q0 += __shfl_xor_sync(0xffffffffu, q0, o);
            s1 += __shfl_xor_sync(0xffffffffu, s1, o);
            q1 += __shfl_xor_sync(0xffffffffu, q1, o);
        }
        if (tg == 0) {
            atomicAdd(&g_sum[n*CO + co0], s0);
            atomicAdd(&g_sq [n*CO + co0], q0);
            atomicAdd(&g_sum[n*CO + co1], s1);
            atomicAdd(&g_sq [n*CO + co1], q1);
        }
    }
}

// ---------------- normalize + affine + ReLU (fp16 in, fp32 out) ----------------
__global__ __launch_bounds__(256)
void norm_kernel(const float* __restrict__ gamma, const float* __restrict__ beta,
                 float* __restrict__ out)
{
    const int inst = blockIdx.x;
    const int c = inst & (CO - 1);
    const float mean = g_sum[inst] * (1.0f / HWSZ);
    const float var  = g_sq[inst] * (1.0f / HWSZ) - mean * mean;
    const float rstd = rsqrtf(var + EPS);
    const float sc = rstd * gamma[c];
    const float sh = beta[c] - mean * sc;

    const uint4* yp = (const uint4*)(g_y + (size_t)inst * HWSZ);
    float4* op = (float4*)(out + (size_t)inst * HWSZ);
    for (int i = threadIdx.x; i < HWSZ/8; i += 256) {
        uint4 raw = yp[i];
        __half2 h01 = *(__half2*)&raw.x;
        __half2 h23 = *(__half2*)&raw.y;
        __half2 h45 = *(__half2*)&raw.z;
        __half2 h67 = *(__half2*)&raw.w;
        float2 f01 = __half22float2(h01);
        float2 f23 = __half22float2(h23);
        float2 f45 = __half22float2(h45);
        float2 f67 = __half22float2(h67);
        float4 o0, o1;
        o0.x = fmaxf(fmaf(f01.x, sc, sh), 0.0f);
        o0.y = fmaxf(fmaf(f01.y, sc, sh), 0.0f);
        o0.z = fmaxf(fmaf(f23.x, sc, sh), 0.0f);
        o0.w = fmaxf(fmaf(f23.y, sc, sh), 0.0f);
        o1.x = fmaxf(fmaf(f45.x, sc, sh), 0.0f);
        o1.y = fmaxf(fmaf(f45.y, sc, sh), 0.0f);
        o1.z = fmaxf(fmaf(f67.x, sc, sh), 0.0f);
        o1.w = fmaxf(fmaf(f67.y, sc, sh), 0.0f);
        op[i*2]   = o0;
        op[i*2+1] = o1;
    }
}

extern "C" void kernel_launch(void* const* d_in, const int* in_sizes, int n_in,
                              void* d_out, int out_size)
{
    const float* x      = (const float*)d_in[0];
    const float* weight = (const float*)d_in[1];
    const float* bias   = (const float*)d_in[2];
    const float* gamma  = (const float*)d_in[3];
    const float* beta   = (const float*)d_in[4];
    float* out = (float*)d_out;

    cudaFuncSetAttribute(conv_mma_kernel, cudaFuncAttributeMaxDynamicSharedMemorySize, SMEM_TOTAL);

    prep_kernel<<<XT_BLOCKS + PP_BLOCKS, 256>>>(x, weight);
    conv_mma_kernel<<<NN*(HH/ROWS_PER_CTA), CONV_THREADS, SMEM_TOTAL>>>(bias);
    norm_kernel<<<NN*CO, 256>>>(gamma, beta, out);
}

// round 13
// speedup vs baseline: 2.3975x; 1.0498x over previous
#include <cuda_runtime.h>
#include <cuda_fp16.h>
#include <math.h>
#include <stdint.h>

#define NN 8
#define CI 128
#define CO 128
#define HH 128
#define WW 128
#define HWSZ (HH*WW)
#define EPS 1e-5f

#define KC 64                  // ci per chunk
#define NCHUNK 2
#define NTAP 9
#define NSTAGE (NCHUNK*NTAP)   // 18
#define ROWS_PER_CTA 2
#define BROWS 4                // input rows (2 output rows + halo)
#define BCOLS 130              // 128 + 2 halo
#define BPIX (BROWS*BCOLS)     // 520

#define CONV_THREADS 512       // 16 warps

// smem layout (bytes): A triple buffer (16K each), then B chunk0 + chunk1 resident
#define SMEM_B      49152
#define SMEM_B_SZ   (BPIX*128)            // 66560 per chunk
#define SMEM_TOTAL  (SMEM_B + 2*SMEM_B_SZ)  // 182272

// scratch
__device__ __half g_y[(size_t)NN*CO*HH*WW];           // conv output (fp16, 32MB)
__device__ float g_sum[NN*CO];
__device__ float g_sq[NN*CO];
__device__ unsigned char g_wpack[NSTAGE*16384];       // [chunk*9+tap]: swizzled [co][ci] fp16
__device__ __half g_xt[(size_t)NN*130*130*128];       // channel-last fp16 x, halo-padded

// ---------------- helpers ----------------
__device__ __forceinline__ uint32_t smem_u32(const void* p) {
    uint32_t a;
    asm("{ .reg .u64 t; cvta.to.shared.u64 t, %1; cvt.u32.u64 %0, t; }" : "=r"(a) : "l"(p));
    return a;
}
__host__ __device__ __forceinline__ uint32_t swz128(uint32_t off) { return off ^ ((off >> 3) & 0x70); }

__device__ __forceinline__ void ldsm4(uint32_t* r, uint32_t addr) {
    asm volatile("ldmatrix.sync.aligned.m8n8.x4.shared.b16 {%0,%1,%2,%3}, [%4];"
                 : "=r"(r[0]), "=r"(r[1]), "=r"(r[2]), "=r"(r[3]) : "r"(addr));
}
__device__ __forceinline__ void mma16816(float* d, const uint32_t* a, uint32_t b0, uint32_t b1) {
    asm volatile("mma.sync.aligned.m16n8k16.row.col.f32.f16.f16.f32 "
                 "{%0,%1,%2,%3}, {%4,%5,%6,%7}, {%8,%9}, {%0,%1,%2,%3};"
                 : "+f"(d[0]), "+f"(d[1]), "+f"(d[2]), "+f"(d[3])
                 : "r"(a[0]), "r"(a[1]), "r"(a[2]), "r"(a[3]), "r"(b0), "r"(b1));
}
__device__ __forceinline__ void cp_async16(uint32_t dst, const void* src) {
    asm volatile("cp.async.cg.shared.global [%0], [%1], 16;" :: "r"(dst), "l"(src));
}
__device__ __forceinline__ void cp_commit()  { asm volatile("cp.async.commit_group;"); }
__device__ __forceinline__ void cp_wait1()   { asm volatile("cp.async.wait_group 1;" ::: "memory"); }
__device__ __forceinline__ void cp_waitall() { asm volatile("cp.async.wait_group 0;" ::: "memory"); }

// ---------------- fused preprocessing: x transpose + weight prepack ----------------
// blocks [0, 130*NN): x_t rows;  blocks [130*NN, ...): weight prepack + sum zeroing
#define XT_BLOCKS (130*NN)
#define PP_BLOCKS ((CO*CI*NTAP + 255)/256)
__global__ __launch_bounds__(256)
void prep_kernel(const float* __restrict__ x, const float* __restrict__ w)
{
    if (blockIdx.x >= XT_BLOCKS) {
        // ---- weight prepack ----
        int idx = (blockIdx.x - XT_BLOCKS) * 256 + threadIdx.x;
        if (idx < NN*CO) { g_sum[idx] = 0.0f; g_sq[idx] = 0.0f; }
        if (idx >= CO*CI*NTAP) return;
        int t  = idx % 9;
        int ci = (idx / 9) % CI;
        int co = idx / (9*CI);
        __half hi = __float2half(w[idx]);
        int chunk = ci >> 6, cil = ci & 63;
        int img = chunk*NTAP + t;
        uint32_t off = swz128((uint32_t)co*128 + (uint32_t)cil*2);
        *(__half*)(g_wpack + (size_t)img*16384 + off) = hi;
        return;
    }
    // ---- x transpose to channel-last fp16 with halo pad (float4 loads) ----
    __shared__ __half s_t[128*130];   // [gc][ci] padded to 130
    const int row = blockIdx.x % 130;
    const int n   = blockIdx.x / 130;
    const int tid = threadIdx.x;
    __half* outr = g_xt + (size_t)(n*130 + row)*130*128;

    if (row == 0 || row == 129) {
        const uint4 z = {0,0,0,0};
        for (int i = tid; i < 130*128/8; i += 256) ((uint4*)outr)[i] = z;
        return;
    }
    const int gr = row - 1;
    const float4* xp4 = (const float4*)(x + ((size_t)n*CI*HH + gr)*WW);
    #pragma unroll
    for (int it = 0; it < 16; it++) {
        const int idx = it*256 + tid;         // 0..4095
        const int ci = idx >> 5;              // 0..127
        const int g4 = idx & 31;              // 0..31 (float4 index)
        float4 v = xp4[(size_t)ci*(HWSZ/4) + g4];
        const int gc = g4*4;
        s_t[(gc+0)*130 + ci] = __float2half(v.x);
        s_t[(gc+1)*130 + ci] = __float2half(v.y);
        s_t[(gc+2)*130 + ci] = __float2half(v.z);
        s_t[(gc+3)*130 + ci] = __float2half(v.w);
    }
    __syncthreads();
    #pragma unroll
    for (int it = 0; it < 8; it++) {
        const int idx = it*256 + tid;         // 0..2047
        const int gc = idx >> 4, c8 = (idx & 15) * 8;
        __half tmp[8];
        #pragma unroll
        for (int j = 0; j < 8; j++) tmp[j] = s_t[gc*130 + c8 + j];
        *(uint4*)(outr + (size_t)(gc+1)*128 + c8) = *(uint4*)tmp;
    }
    if (tid < 32) {
        const uint4 z = {0,0,0,0};
        if (tid < 16) ((uint4*)(outr))[tid] = z;
        else          ((uint4*)(outr + (size_t)129*128))[tid-16] = z;
    }
}

// ---------------- conv: implicit GEMM via mma.sync fp16, full cp.async pipeline ----------------
__global__ __launch_bounds__(CONV_THREADS, 1)
void conv_mma_kernel(const float* __restrict__ bias)
{
    extern __shared__ __align__(1024) unsigned char smem[];
    const uint32_t sbase = smem_u32(smem);
    const int tid    = threadIdx.x;
    const int lane   = tid & 31;
    const int w      = tid >> 5;       // 0..15
    const int warp_m = w >> 2;         // 0..3 : 32 co each
    const int warp_n = w & 3;          // 0..3 : 64 pixels each
    const int hrow   = warp_n >> 1;
    const int colb   = (warp_n & 1) * 64;

    const int n  = blockIdx.x >> 6;
    const int r0 = (blockIdx.x & 63) * ROWS_PER_CTA;

    const int mtx   = lane >> 3;
    const int rowin = lane & 7;

    const uint32_t kca = (uint32_t)((mtx >> 1) * 16);
    uint32_t aoff[2], axr[2];
    #pragma unroll
    for (int mt = 0; mt < 2; mt++) {
        int co = warp_m*32 + mt*16 + (mtx & 1)*8 + rowin;
        aoff[mt] = (uint32_t)co * 128;
        axr[mt]  = (uint32_t)(co & 7) << 4;
    }
    const uint32_t kcb = (uint32_t)((mtx & 1) * 16);

    float acc[2][8][4];
    #pragma unroll
    for (int mt = 0; mt < 2; mt++)
        #pragma unroll
        for (int nt = 0; nt < 8; nt++)
            #pragma unroll
            for (int i = 0; i < 4; i++)
                acc[mt][nt][i] = 0.0f;

    const __half* xtn = g_xt + (size_t)n*130*130*128;

    // prologue: B chunk0 (group 0), A stage0 (group 1)
    for (int u = tid; u < BPIX*8; u += CONV_THREADS) {
        const int pix = u >> 3, j = u & 7;
        const int rho = pix / BCOLS, oc = pix - rho*BCOLS;
        const char* src = (const char*)(xtn + ((size_t)(r0 + rho)*130 + oc)*128) + j*16;
        cp_async16(sbase + SMEM_B + swz128((uint32_t)pix*128 + j*16), src);
    }
    cp_commit();
    {
        const uint4* src = (const uint4*)g_wpack;
        cp_async16(sbase + (uint32_t)tid*16,         src + tid);
        cp_async16(sbase + (uint32_t)(tid + 512)*16, src + tid + 512);
    }
    cp_commit();

    for (int s = 0; s < NSTAGE; s++) {
        bool issued = false;
        if (s + 1 < NSTAGE) {
            const uint4* src = (const uint4*)(g_wpack + (size_t)(s+1)*16384);
            const uint32_t dst = sbase + (uint32_t)((s+1) % 3) * 16384;
            cp_async16(dst + (uint32_t)tid*16,       src + tid);
            cp_async16(dst + (uint32_t)(tid+512)*16, src + tid + 512);
            issued = true;
        }
        if (s < 8) {
            for (int u = s*520 + tid; u < (s+1)*520; u += CONV_THREADS) {
                const int pix = u >> 3, j = u & 7;
                const int rho = pix / BCOLS, oc = pix - rho*BCOLS;
                const char* src = (const char*)(xtn + ((size_t)(r0 + rho)*130 + oc)*128 + 64) + j*16;
                cp_async16(sbase + SMEM_B + SMEM_B_SZ + swz128((uint32_t)pix*128 + j*16), src);
            }
            issued = true;
        }
        if (issued) { cp_commit(); cp_wait1(); }
        else        { cp_waitall(); }
        __syncthreads();

        const int chunk = s / NTAP;
        const int tap   = s - chunk*NTAP;
        const uint32_t a_base = sbase + (uint32_t)(s % 3) * 16384;
        const uint32_t b_base = sbase + SMEM_B + (uint32_t)chunk * SMEM_B_SZ;
        const int kh = tap / 3, kw = tap - kh*3;
        uint32_t boff[4], bxr[4];
        #pragma unroll
        for (int p = 0; p < 4; p++) {
            int pix = (hrow + kh)*BCOLS + colb + p*16 + (mtx >> 1)*8 + rowin + kw;
            boff[p] = (uint32_t)pix * 128;
            bxr[p]  = (uint32_t)(pix & 7) << 4;
        }

        #pragma unroll
        for (int ks = 0; ks < 4; ks++) {
            uint32_t ah[2][4];
            #pragma unroll
            for (int mt = 0; mt < 2; mt++) {
                const uint32_t ka = (uint32_t)ks*32 + kca;
                ldsm4(ah[mt], a_base + aoff[mt] + (ka ^ axr[mt]));
            }
            #pragma unroll
            for (int p = 0; p < 4; p++) {
                uint32_t bh[4];
                const uint32_t kb = (uint32_t)ks*32 + kcb;
                ldsm4(bh, b_base + boff[p] + (kb ^ bxr[p]));
                #pragma unroll
                for (int mt = 0; mt < 2; mt++)
                    #pragma unroll
                    for (int q = 0; q < 2; q++) {
                        float* a4 = acc[mt][p*2 + q];
                        mma16816(a4, ah[mt], bh[q*2], bh[q*2+1]);
                    }
            }
        }
    }

    // ---- epilogue: bias + fp16 store + instance sums (fp32) ----
    const int g  = lane >> 2;
    const int tg = lane & 3;
    const int row = r0 + hrow;
    #pragma unroll
    for (int mt = 0; mt < 2; mt++) {
        const int co0 = warp_m*32 + mt*16 + g;
        const int co1 = co0 + 8;
        const float b0 = __ldg(bias + co0);
        const float b1 = __ldg(bias + co1);
        __half* yp0 = g_y + ((size_t)(n*CO + co0) * HH + row) * WW;
        __half* yp1 = g_y + ((size_t)(n*CO + co1) * HH + row) * WW;
        float s0 = 0.f, q0 = 0.f, s1 = 0.f, q1 = 0.f;
        #pragma unroll
        for (int nt = 0; nt < 8; nt++) {
            const int pix = colb + nt*8 + 2*tg;
            float v0 = acc[mt][nt][0] + b0;
            float v1 = acc[mt][nt][1] + b0;
            float v2 = acc[mt][nt][2] + b1;
            float v3 = acc[mt][nt][3] + b1;
            *(__half2*)(yp0 + pix) = __floats2half2_rn(v0, v1);
            *(__half2*)(yp1 + pix) = __floats2half2_rn(v2, v3);
            s0 += v0 + v1;  q0 += v0*v0 + v1*v1;
            s1 += v2 + v3;  q1 += v2*v2 + v3*v3;
        }
        #pragma unroll
        for (int o = 1; o <= 2; o <<= 1) {
            s0 += __shfl_xor_sync(0xffffffffu, s0, o);
            q0 += __shfl_xor_sync(0xffffffffu, q0, o);
            s1 += __shfl_xor_sync(0xffffffffu, s1, o);
            q1 += __shfl_xor_sync(0xffffffffu, q1, o);
        }
        if (tg == 0) {
            atomicAdd(&g_sum[n*CO + co0], s0);
            atomicAdd(&g_sq [n*CO + co0], q0);
            atomicAdd(&g_sum[n*CO + co1], s1);
            atomicAdd(&g_sq [n*CO + co1], q1);
        }
    }
}

// ---------------- normalize + affine + ReLU (fp16 in, fp32 out) ----------------
// 2 blocks per instance for higher memory-level parallelism.
__global__ __launch_bounds__(256)
void norm_kernel(const float* __restrict__ gamma, const float* __restrict__ beta,
                 float* __restrict__ out)
{
    const int inst = blockIdx.x >> 1;
    const int half = blockIdx.x & 1;
    const int c = inst & (CO - 1);
    const float mean = g_sum[inst] * (1.0f / HWSZ);
    const float var  = g_sq[inst] * (1.0f / HWSZ) - mean * mean;
    const float rstd = rsqrtf(var + EPS);
    const float sc = rstd * gamma[c];
    const float sh = beta[c] - mean * sc;

    const uint4* yp = (const uint4*)(g_y + (size_t)inst * HWSZ) + (size_t)half * (HWSZ/16);
    float4* op = (float4*)(out + (size_t)inst * HWSZ) + (size_t)half * (HWSZ/8);
    #pragma unroll 2
    for (int i = threadIdx.x; i < HWSZ/16; i += 256) {
        uint4 raw = yp[i];
        float2 f01 = __half22float2(*(__half2*)&raw.x);
        float2 f23 = __half22float2(*(__half2*)&raw.y);
        float2 f45 = __half22float2(*(__half2*)&raw.z);
        float2 f67 = __half22float2(*(__half2*)&raw.w);
        float4 o0, o1;
        o0.x = fmaxf(fmaf(f01.x, sc, sh), 0.0f);
        o0.y = fmaxf(fmaf(f01.y, sc, sh), 0.0f);
        o0.z = fmaxf(fmaf(f23.x, sc, sh), 0.0f);
        o0.w = fmaxf(fmaf(f23.y, sc, sh), 0.0f);
        o1.x = fmaxf(fmaf(f45.x, sc, sh), 0.0f);
        o1.y = fmaxf(fmaf(f45.y, sc, sh), 0.0f);
        o1.z = fmaxf(fmaf(f67.x, sc, sh), 0.0f);
        o1.w = fmaxf(fmaf(f67.y, sc, sh), 0.0f);
        op[i*2]   = o0;
        op[i*2+1] = o1;
    }
}

extern "C" void kernel_launch(void* const* d_in, const int* in_sizes, int n_in,
                              void* d_out, int out_size)
{
    const float* x      = (const float*)d_in[0];
    const float* weight = (const float*)d_in[1];
    const float* bias   = (const float*)d_in[2];
    const float* gamma  = (const float*)d_in[3];
    const float* beta   = (const float*)d_in[4];
    float* out = (float*)d_out;

    cudaFuncSetAttribute(conv_mma_kernel, cudaFuncAttributeMaxDynamicSharedMemorySize, SMEM_TOTAL);

    prep_kernel<<<XT_BLOCKS + PP_BLOCKS, 256>>>(x, weight);
    conv_mma_kernel<<<NN*(HH/ROWS_PER_CTA), CONV_THREADS, SMEM_TOTAL>>>(bias);
    norm_kernel<<<NN*CO*2, 256>>>(gamma, beta, out);
}

// round 14
// speedup vs baseline: 2.4193x; 1.0091x over previous
#include <cuda_runtime.h>
#include <cuda_fp16.h>
#include <math.h>
#include <stdint.h>

#define NN 8
#define CI 128
#define CO 128
#define HH 128
#define WW 128
#define HWSZ (HH*WW)
#define EPS 1e-5f

#define KC 64                  // ci per chunk
#define NCHUNK 2
#define NTAP 9
#define NSTAGE (NCHUNK*NTAP)   // 18
#define ROWS_PER_CTA 2
#define BROWS 4                // input rows (2 output rows + halo)
#define BCOLS 130              // 128 + 2 halo
#define BPIX (BROWS*BCOLS)     // 520

#define CONV_THREADS 512       // 16 warps

// smem layout (bytes): A triple buffer (16K each), then B chunk0 + chunk1 resident
#define SMEM_B      49152
#define SMEM_B_SZ   (BPIX*128)            // 66560 per chunk
#define SMEM_TOTAL  (SMEM_B + 2*SMEM_B_SZ)  // 182272

// scratch
__device__ __half g_y[(size_t)NN*CO*HH*WW];           // conv output (fp16, 32MB)
__device__ float g_sum[NN*CO];
__device__ float g_sq[NN*CO];
__device__ unsigned char g_wpack[NSTAGE*16384];       // [chunk*9+tap]: swizzled [co][ci] fp16
__device__ __half g_xt[(size_t)NN*130*130*128];       // channel-last fp16 x, halo-padded

// ---------------- helpers ----------------
__device__ __forceinline__ uint32_t smem_u32(const void* p) {
    uint32_t a;
    asm("{ .reg .u64 t; cvta.to.shared.u64 t, %1; cvt.u32.u64 %0, t; }" : "=r"(a) : "l"(p));
    return a;
}
__host__ __device__ __forceinline__ uint32_t swz128(uint32_t off) { return off ^ ((off >> 3) & 0x70); }

__device__ __forceinline__ void ldsm4(uint32_t* r, uint32_t addr) {
    asm volatile("ldmatrix.sync.aligned.m8n8.x4.shared.b16 {%0,%1,%2,%3}, [%4];"
                 : "=r"(r[0]), "=r"(r[1]), "=r"(r[2]), "=r"(r[3]) : "r"(addr));
}
__device__ __forceinline__ void mma16816(float* d, const uint32_t* a, uint32_t b0, uint32_t b1) {
    asm volatile("mma.sync.aligned.m16n8k16.row.col.f32.f16.f16.f32 "
                 "{%0,%1,%2,%3}, {%4,%5,%6,%7}, {%8,%9}, {%0,%1,%2,%3};"
                 : "+f"(d[0]), "+f"(d[1]), "+f"(d[2]), "+f"(d[3])
                 : "r"(a[0]), "r"(a[1]), "r"(a[2]), "r"(a[3]), "r"(b0), "r"(b1));
}
__device__ __forceinline__ void cp_async16(uint32_t dst, const void* src) {
    asm volatile("cp.async.cg.shared.global [%0], [%1], 16;" :: "r"(dst), "l"(src));
}
__device__ __forceinline__ void cp_commit()  { asm volatile("cp.async.commit_group;"); }
__device__ __forceinline__ void cp_wait1()   { asm volatile("cp.async.wait_group 1;" ::: "memory"); }
__device__ __forceinline__ void cp_waitall() { asm volatile("cp.async.wait_group 0;" ::: "memory"); }

// ---------------- fused preprocessing: x transpose + weight prepack ----------------
// blocks [0, 130*NN): x_t rows;  blocks [130*NN, ...): weight prepack + sum zeroing
#define XT_BLOCKS (130*NN)
#define PP_BLOCKS ((CO*CI*NTAP + 255)/256)
__global__ __launch_bounds__(256)
void prep_kernel(const float* __restrict__ x, const float* __restrict__ w)
{
    if (blockIdx.x >= XT_BLOCKS) {
        // ---- weight prepack ----
        int idx = (blockIdx.x - XT_BLOCKS) * 256 + threadIdx.x;
        if (idx < NN*CO) { g_sum[idx] = 0.0f; g_sq[idx] = 0.0f; }
        if (idx >= CO*CI*NTAP) return;
        int t  = idx % 9;
        int ci = (idx / 9) % CI;
        int co = idx / (9*CI);
        __half hi = __float2half(w[idx]);
        int chunk = ci >> 6, cil = ci & 63;
        int img = chunk*NTAP + t;
        uint32_t off = swz128((uint32_t)co*128 + (uint32_t)cil*2);
        *(__half*)(g_wpack + (size_t)img*16384 + off) = hi;
        return;
    }
    // ---- x transpose to channel-last fp16 with halo pad ----
    // Stores as half2 {ci, ci+1}: lane bank step = 2 -> <=2-way conflicts.
    __shared__ __half s_t[128*130];   // [gc][ci], row stride 130 halfs
    const int row = blockIdx.x % 130;
    const int n   = blockIdx.x / 130;
    const int tid = threadIdx.x;
    __half* outr = g_xt + (size_t)(n*130 + row)*130*128;

    if (row == 0 || row == 129) {
        const uint4 z = {0,0,0,0};
        for (int i = tid; i < 130*128/8; i += 256) ((uint4*)outr)[i] = z;
        return;
    }
    const int gr = row - 1;
    const float4* xp4 = (const float4*)(x + ((size_t)n*CI*HH + gr)*WW);
    #pragma unroll
    for (int it = 0; it < 8; it++) {
        const int idx = it*256 + tid;         // 0..2047
        const int cp  = idx >> 5;             // ci pair 0..63
        const int g4  = idx & 31;             // float4 index within row
        const int ci0 = cp*2;
        float4 v0 = xp4[(size_t)(ci0  )*(HWSZ/4) + g4];
        float4 v1 = xp4[(size_t)(ci0+1)*(HWSZ/4) + g4];
        const int gc = g4*4;
        *(__half2*)&s_t[(gc+0)*130 + ci0] = __floats2half2_rn(v0.x, v1.x);
        *(__half2*)&s_t[(gc+1)*130 + ci0] = __floats2half2_rn(v0.y, v1.y);
        *(__half2*)&s_t[(gc+2)*130 + ci0] = __floats2half2_rn(v0.z, v1.z);
        *(__half2*)&s_t[(gc+3)*130 + ci0] = __floats2half2_rn(v0.w, v1.w);
    }
    __syncthreads();
    #pragma unroll
    for (int it = 0; it < 8; it++) {
        const int idx = it*256 + tid;         // 0..2047
        const int gc = idx >> 4, c8 = (idx & 15) * 8;
        __half tmp[8];
        #pragma unroll
        for (int j = 0; j < 8; j++) tmp[j] = s_t[gc*130 + c8 + j];
        *(uint4*)(outr + (size_t)(gc+1)*128 + c8) = *(uint4*)tmp;
    }
    if (tid < 32) {
        const uint4 z = {0,0,0,0};
        if (tid < 16) ((uint4*)(outr))[tid] = z;
        else          ((uint4*)(outr + (size_t)129*128))[tid-16] = z;
    }
}

// ---------------- conv: implicit GEMM via mma.sync fp16, full cp.async pipeline ----------------
__global__ __launch_bounds__(CONV_THREADS, 1)
void conv_mma_kernel(const float* __restrict__ bias)
{
    extern __shared__ __align__(1024) unsigned char smem[];
    const uint32_t sbase = smem_u32(smem);
    const int tid    = threadIdx.x;
    const int lane   = tid & 31;
    const int w      = tid >> 5;       // 0..15
    const int warp_m = w >> 2;         // 0..3 : 32 co each
    const int warp_n = w & 3;          // 0..3 : 64 pixels each
    const int hrow   = warp_n >> 1;
    const int colb   = (warp_n & 1) * 64;

    const int n  = blockIdx.x >> 6;
    const int r0 = (blockIdx.x & 63) * ROWS_PER_CTA;

    const int mtx   = lane >> 3;
    const int rowin = lane & 7;

    const uint32_t kca = (uint32_t)((mtx >> 1) * 16);
    uint32_t aoff[2], axr[2];
    #pragma unroll
    for (int mt = 0; mt < 2; mt++) {
        int co = warp_m*32 + mt*16 + (mtx & 1)*8 + rowin;
        aoff[mt] = (uint32_t)co * 128;
        axr[mt]  = (uint32_t)(co & 7) << 4;
    }
    const uint32_t kcb = (uint32_t)((mtx & 1) * 16);

    float acc[2][8][4];
    #pragma unroll
    for (int mt = 0; mt < 2; mt++)
        #pragma unroll
        for (int nt = 0; nt < 8; nt++)
            #pragma unroll
            for (int i = 0; i < 4; i++)
                acc[mt][nt][i] = 0.0f;

    const __half* xtn = g_xt + (size_t)n*130*130*128;

    // prologue: B chunk0 (group 0), A stage0 (group 1)
    for (int u = tid; u < BPIX*8; u += CONV_THREADS) {
        const int pix = u >> 3, j = u & 7;
        const int rho = pix / BCOLS, oc = pix - rho*BCOLS;
        const char* src = (const char*)(xtn + ((size_t)(r0 + rho)*130 + oc)*128) + j*16;
        cp_async16(sbase + SMEM_B + swz128((uint32_t)pix*128 + j*16), src);
    }
    cp_commit();
    {
        const uint4* src = (const uint4*)g_wpack;
        cp_async16(sbase + (uint32_t)tid*16,         src + tid);
        cp_async16(sbase + (uint32_t)(tid + 512)*16, src + tid + 512);
    }
    cp_commit();

    for (int s = 0; s < NSTAGE; s++) {
        bool issued = false;
        if (s + 1 < NSTAGE) {
            const uint4* src = (const uint4*)(g_wpack + (size_t)(s+1)*16384);
            const uint32_t dst = sbase + (uint32_t)((s+1) % 3) * 16384;
            cp_async16(dst + (uint32_t)tid*16,       src + tid);
            cp_async16(dst + (uint32_t)(tid+512)*16, src + tid + 512);
            issued = true;
        }
        if (s < 8) {
            for (int u = s*520 + tid; u < (s+1)*520; u += CONV_THREADS) {
                const int pix = u >> 3, j = u & 7;
                const int rho = pix / BCOLS, oc = pix - rho*BCOLS;
                const char* src = (const char*)(xtn + ((size_t)(r0 + rho)*130 + oc)*128 + 64) + j*16;
                cp_async16(sbase + SMEM_B + SMEM_B_SZ + swz128((uint32_t)pix*128 + j*16), src);
            }
            issued = true;
        }
        if (issued) { cp_commit(); cp_wait1(); }
        else        { cp_waitall(); }
        __syncthreads();

        const int chunk = s / NTAP;
        const int tap   = s - chunk*NTAP;
        const uint32_t a_base = sbase + (uint32_t)(s % 3) * 16384;
        const uint32_t b_base = sbase + SMEM_B + (uint32_t)chunk * SMEM_B_SZ;
        const int kh = tap / 3, kw = tap - kh*3;
        uint32_t boff[4], bxr[4];
        #pragma unroll
        for (int p = 0; p < 4; p++) {
            int pix = (hrow + kh)*BCOLS + colb + p*16 + (mtx >> 1)*8 + rowin + kw;
            boff[p] = (uint32_t)pix * 128;
            bxr[p]  = (uint32_t)(pix & 7) << 4;
        }

        #pragma unroll
        for (int ks = 0; ks < 4; ks++) {
            uint32_t ah[2][4];
            #pragma unroll
            for (int mt = 0; mt < 2; mt++) {
                const uint32_t ka = (uint32_t)ks*32 + kca;
                ldsm4(ah[mt], a_base + aoff[mt] + (ka ^ axr[mt]));
            }
            #pragma unroll
            for (int p = 0; p < 4; p++) {
                uint32_t bh[4];
                const uint32_t kb = (uint32_t)ks*32 + kcb;
                ldsm4(bh, b_base + boff[p] + (kb ^ bxr[p]));
                #pragma unroll
                for (int mt = 0; mt < 2; mt++)
                    #pragma unroll
                    for (int q = 0; q < 2; q++) {
                        float* a4 = acc[mt][p*2 + q];
                        mma16816(a4, ah[mt], bh[q*2], bh[q*2+1]);
                    }
            }
        }
    }

    // ---- epilogue: bias + fp16 store + instance sums (fp32) ----
    const int g  = lane >> 2;
    const int tg = lane & 3;
    const int row = r0 + hrow;
    #pragma unroll
    for (int mt = 0; mt < 2; mt++) {
        const int co0 = warp_m*32 + mt*16 + g;
        const int co1 = co0 + 8;
        const float b0 = __ldg(bias + co0);
        const float b1 = __ldg(bias + co1);
        __half* yp0 = g_y + ((size_t)(n*CO + co0) * HH + row) * WW;
        __half* yp1 = g_y + ((size_t)(n*CO + co1) * HH + row) * WW;
        float s0 = 0.f, q0 = 0.f, s1 = 0.f, q1 = 0.f;
        #pragma unroll
        for (int nt = 0; nt < 8; nt++) {
            const int pix = colb + nt*8 + 2*tg;
            float v0 = acc[mt][nt][0] + b0;
            float v1 = acc[mt][nt][1] + b0;
            float v2 = acc[mt][nt][2] + b1;
            float v3 = acc[mt][nt][3] + b1;
            *(__half2*)(yp0 + pix) = __floats2half2_rn(v0, v1);
            *(__half2*)(yp1 + pix) = __floats2half2_rn(v2, v3);
            s0 += v0 + v1;  q0 += v0*v0 + v1*v1;
            s1 += v2 + v3;  q1 += v2*v2 + v3*v3;
        }
        #pragma unroll
        for (int o = 1; o <= 2; o <<= 1) {
            s0 += __shfl_xor_sync(0xffffffffu, s0, o);
            q0 += __shfl_xor_sync(0xffffffffu, q0, o);
            s1 += __shfl_xor_sync(0xffffffffu, s1, o);
            q1 += __shfl_xor_sync(0xffffffffu, q1, o);
        }
        if (tg == 0) {
            atomicAdd(&g_sum[n*CO + co0], s0);
            atomicAdd(&g_sq [n*CO + co0], q0);
            atomicAdd(&g_sum[n*CO + co1], s1);
            atomicAdd(&g_sq [n*CO + co1], q1);
        }
    }
}

// ---------------- normalize + affine + ReLU (fp16 in, fp32 out) ----------------
// 2 blocks per instance for higher memory-level parallelism.
__global__ __launch_bounds__(256)
void norm_kernel(const float* __restrict__ gamma, const float* __restrict__ beta,
                 float* __restrict__ out)
{
    const int inst = blockIdx.x >> 1;
    const int half = blockIdx.x & 1;
    const int c = inst & (CO - 1);
    const float mean = g_sum[inst] * (1.0f / HWSZ);
    const float var  = g_sq[inst] * (1.0f / HWSZ) - mean * mean;
    const float rstd = rsqrtf(var + EPS);
    const float sc = rstd * gamma[c];
    const float sh = beta[c] - mean * sc;

    const uint4* yp = (const uint4*)(g_y + (size_t)inst * HWSZ) + (size_t)half * (HWSZ/16);
    float4* op = (float4*)(out + (size_t)inst * HWSZ) + (size_t)half * (HWSZ/8);
    #pragma unroll 2
    for (int i = threadIdx.x; i < HWSZ/16; i += 256) {
        uint4 raw = yp[i];
        float2 f01 = __half22float2(*(__half2*)&raw.x);
        float2 f23 = __half22float2(*(__half2*)&raw.y);
        float2 f45 = __half22float2(*(__half2*)&raw.z);
        float2 f67 = __half22float2(*(__half2*)&raw.w);
        float4 o0, o1;
        o0.x = fmaxf(fmaf(f01.x, sc, sh), 0.0f);
        o0.y = fmaxf(fmaf(f01.y, sc, sh), 0.0f);
        o0.z = fmaxf(fmaf(f23.x, sc, sh), 0.0f);
        o0.w = fmaxf(fmaf(f23.y, sc, sh), 0.0f);
        o1.x = fmaxf(fmaf(f45.x, sc, sh), 0.0f);
        o1.y = fmaxf(fmaf(f45.y, sc, sh), 0.0f);
        o1.z = fmaxf(fmaf(f67.x, sc, sh), 0.0f);
        o1.w = fmaxf(fmaf(f67.y, sc, sh), 0.0f);
        op[i*2]   = o0;
        op[i*2+1] = o1;
    }
}

extern "C" void kernel_launch(void* const* d_in, const int* in_sizes, int n_in,
                              void* d_out, int out_size)
{
    const float* x      = (const float*)d_in[0];
    const float* weight = (const float*)d_in[1];
    const float* bias   = (const float*)d_in[2];
    const float* gamma  = (const float*)d_in[3];
    const float* beta   = (const float*)d_in[4];
    float* out = (float*)d_out;

    cudaFuncSetAttribute(conv_mma_kernel, cudaFuncAttributeMaxDynamicSharedMemorySize, SMEM_TOTAL);

    prep_kernel<<<XT_BLOCKS + PP_BLOCKS, 256>>>(x, weight);
    conv_mma_kernel<<<NN*(HH/ROWS_PER_CTA), CONV_THREADS, SMEM_TOTAL>>>(bias);
    norm_kernel<<<NN*CO*2, 256>>>(gamma, beta, out);
}